// round 2
// baseline (speedup 1.0000x reference)
#include <cuda_runtime.h>
#include <cstdint>

// ---------------------------------------------------------------------------
// AttentionS2: B=1, C=512, HEADS=8, hd=64, tokens HW=4096 (64x64 grid)
//
//   x (512 x 4096)  --1x1 conv (3x)-->  q,k,v  token-major (4096 x 512)
//   per head: softmax(QK^T * 0.125 + log_quad_w) @ V  -> o (4096 x 512)
//   out (512 x 4096) = p_w @ o^T + p_b
// ---------------------------------------------------------------------------

#define NTOK 4096
#define CIN  512
#define HEADS 8
#define HD 64

// Scratch (device globals: no allocations allowed)
__device__ float g_q[NTOK * CIN];
__device__ float g_k[NTOK * CIN];
__device__ float g_v[NTOK * CIN];
__device__ float g_o[NTOK * CIN];

__device__ __forceinline__ float dot4(float4 a, float4 b) {
    return a.x*b.x + a.y*b.y + a.z*b.z + a.w*b.w;
}

// ---------------------------------------------------------------------------
// Kernel 1: fused QKV projection.
// out[t][o] = sum_i x[i][t] * w[o][i] + b[o]
// grid: (64 token-tiles, 24 n-tiles: 8 each for q,k,v). 256 thr, 4x4/thread.
// ---------------------------------------------------------------------------
__global__ __launch_bounds__(256)
void qkv_proj_kernel(const float* __restrict__ x,
                     const float* __restrict__ qw, const float* __restrict__ qb,
                     const float* __restrict__ kw, const float* __restrict__ kb,
                     const float* __restrict__ vw, const float* __restrict__ vb)
{
    __shared__ float As[32][64];   // As[k][t]
    __shared__ float Bs[32][68];   // Bs[k][o] (padded)

    const int tid = threadIdx.x;
    const int tx = tid & 15, ty = tid >> 4;
    const int t0 = blockIdx.x * 64;
    const int nt = blockIdx.y;
    const int which = nt >> 3;           // 0=q 1=k 2=v
    const int o0 = (nt & 7) * 64;

    const float* w   = (which == 0) ? qw : (which == 1) ? kw : vw;
    const float* b   = (which == 0) ? qb : (which == 1) ? kb : vb;
    float*       out = (which == 0) ? g_q : (which == 1) ? g_k : g_v;

    float acc[4][4] = {};

    const int akr = tid >> 3, atc = (tid & 7) * 8;   // A load map
    const int bor = tid >> 2, bkc = (tid & 3) * 8;   // B load map

    for (int k0 = 0; k0 < CIN; k0 += 32) {
        {
            const float* ap = x + (size_t)(k0 + akr) * NTOK + t0 + atc;
            float4 a0 = *(const float4*)ap;
            float4 a1 = *(const float4*)(ap + 4);
            *(float4*)&As[akr][atc]     = a0;
            *(float4*)&As[akr][atc + 4] = a1;
        }
        {
            const float* bp = w + (size_t)(o0 + bor) * CIN + k0 + bkc;
            float4 b0 = *(const float4*)bp;
            float4 b1 = *(const float4*)(bp + 4);
            Bs[bkc+0][bor] = b0.x; Bs[bkc+1][bor] = b0.y;
            Bs[bkc+2][bor] = b0.z; Bs[bkc+3][bor] = b0.w;
            Bs[bkc+4][bor] = b1.x; Bs[bkc+5][bor] = b1.y;
            Bs[bkc+6][bor] = b1.z; Bs[bkc+7][bor] = b1.w;
        }
        __syncthreads();
        #pragma unroll
        for (int k = 0; k < 32; k++) {
            float4 av = *(const float4*)&As[k][ty * 4];
            float4 bv = *(const float4*)&Bs[k][tx * 4];
            acc[0][0] += av.x*bv.x; acc[0][1] += av.x*bv.y; acc[0][2] += av.x*bv.z; acc[0][3] += av.x*bv.w;
            acc[1][0] += av.y*bv.x; acc[1][1] += av.y*bv.y; acc[1][2] += av.y*bv.z; acc[1][3] += av.y*bv.w;
            acc[2][0] += av.z*bv.x; acc[2][1] += av.z*bv.y; acc[2][2] += av.z*bv.z; acc[2][3] += av.z*bv.w;
            acc[3][0] += av.w*bv.x; acc[3][1] += av.w*bv.y; acc[3][2] += av.w*bv.z; acc[3][3] += av.w*bv.w;
        }
        __syncthreads();
    }

    float4 bias = *(const float4*)&b[o0 + tx * 4];
    #pragma unroll
    for (int i = 0; i < 4; i++) {
        float4 r;
        r.x = acc[i][0] + bias.x; r.y = acc[i][1] + bias.y;
        r.z = acc[i][2] + bias.z; r.w = acc[i][3] + bias.w;
        *(float4*)&out[(size_t)(t0 + ty * 4 + i) * CIN + o0 + tx * 4] = r;
    }
}

// ---------------------------------------------------------------------------
// Kernel 2: flash attention per (head, 64-query tile).
// 256 threads: thread (ty,tx) owns 4 q-rows x 4 (key or d) cols.
// Row softmax stats reduced across tx (16-lane shuffle groups).
// ---------------------------------------------------------------------------
__global__ __launch_bounds__(256)
void attn_kernel(const float* __restrict__ lqw)
{
    extern __shared__ float sm[];
    float* Qs = sm;               // 64 x 68
    float* Ks = Qs + 64 * 68;
    float* Vs = Ks + 64 * 68;
    float* Ps = Vs + 64 * 68;

    const int tid = threadIdx.x;
    const int tx = tid & 15, ty = tid >> 4;
    const int h  = blockIdx.y;
    const int q0 = blockIdx.x * 64;
    const float scale = 0.125f;   // 1/sqrt(64)

    const int lr = tid >> 2, lc = (tid & 3) * 16;

    // load Q tile
    {
        const float* src = g_q + (size_t)(q0 + lr) * CIN + h * HD + lc;
        float* dst = &Qs[lr * 68 + lc];
        #pragma unroll
        for (int u = 0; u < 16; u += 4)
            *(float4*)(dst + u) = *(const float4*)(src + u);
    }

    float O[4][4];
    float m_i[4], l_i[4];
    #pragma unroll
    for (int i = 0; i < 4; i++) {
        m_i[i] = -1e30f; l_i[i] = 0.f;
        O[i][0] = O[i][1] = O[i][2] = O[i][3] = 0.f;
    }

    for (int kt = 0; kt < NTOK / 64; kt++) {
        // load K, V tiles
        {
            const float* ks = g_k + (size_t)(kt * 64 + lr) * CIN + h * HD + lc;
            const float* vs = g_v + (size_t)(kt * 64 + lr) * CIN + h * HD + lc;
            float* kd = &Ks[lr * 68 + lc];
            float* vd = &Vs[lr * 68 + lc];
            #pragma unroll
            for (int u = 0; u < 16; u += 4) {
                *(float4*)(kd + u) = *(const float4*)(ks + u);
                *(float4*)(vd + u) = *(const float4*)(vs + u);
            }
        }
        __syncthreads();

        // S = Q K^T (64x64x64 tile)
        float s[4][4] = {};
        #pragma unroll
        for (int dd = 0; dd < 64; dd += 4) {
            float4 a0 = *(const float4*)&Qs[(ty*4+0)*68 + dd];
            float4 a1 = *(const float4*)&Qs[(ty*4+1)*68 + dd];
            float4 a2 = *(const float4*)&Qs[(ty*4+2)*68 + dd];
            float4 a3 = *(const float4*)&Qs[(ty*4+3)*68 + dd];
            float4 b0 = *(const float4*)&Ks[(tx*4+0)*68 + dd];
            float4 b1 = *(const float4*)&Ks[(tx*4+1)*68 + dd];
            float4 b2 = *(const float4*)&Ks[(tx*4+2)*68 + dd];
            float4 b3 = *(const float4*)&Ks[(tx*4+3)*68 + dd];
            s[0][0] += dot4(a0,b0); s[0][1] += dot4(a0,b1); s[0][2] += dot4(a0,b2); s[0][3] += dot4(a0,b3);
            s[1][0] += dot4(a1,b0); s[1][1] += dot4(a1,b1); s[1][2] += dot4(a1,b2); s[1][3] += dot4(a1,b3);
            s[2][0] += dot4(a2,b0); s[2][1] += dot4(a2,b1); s[2][2] += dot4(a2,b2); s[2][3] += dot4(a2,b3);
            s[3][0] += dot4(a3,b0); s[3][1] += dot4(a3,b1); s[3][2] += dot4(a3,b2); s[3][3] += dot4(a3,b3);
        }

        // online softmax (scale + log-quadrature bias over keys)
        float4 lbv = *(const float4*)&lqw[kt * 64 + tx * 4];
        #pragma unroll
        for (int i = 0; i < 4; i++) {
            float r0 = s[i][0]*scale + lbv.x;
            float r1 = s[i][1]*scale + lbv.y;
            float r2 = s[i][2]*scale + lbv.z;
            float r3 = s[i][3]*scale + lbv.w;
            float rmax = fmaxf(fmaxf(r0, r1), fmaxf(r2, r3));
            #pragma unroll
            for (int off = 1; off < 16; off <<= 1)
                rmax = fmaxf(rmax, __shfl_xor_sync(0xffffffffu, rmax, off));
            float mn = fmaxf(m_i[i], rmax);
            float alpha = __expf(m_i[i] - mn);
            m_i[i] = mn;
            float p0 = __expf(r0 - mn);
            float p1 = __expf(r1 - mn);
            float p2 = __expf(r2 - mn);
            float p3 = __expf(r3 - mn);
            float4 pv; pv.x = p0; pv.y = p1; pv.z = p2; pv.w = p3;
            *(float4*)&Ps[(ty*4+i)*68 + tx*4] = pv;
            float rsum = p0 + p1 + p2 + p3;
            #pragma unroll
            for (int off = 1; off < 16; off <<= 1)
                rsum += __shfl_xor_sync(0xffffffffu, rsum, off);
            l_i[i] = l_i[i] * alpha + rsum;
            O[i][0] *= alpha; O[i][1] *= alpha; O[i][2] *= alpha; O[i][3] *= alpha;
        }
        __syncthreads();

        // O += P V  (64x64x64 tile; tx now indexes d)
        #pragma unroll
        for (int kc = 0; kc < 64; kc += 4) {
            float4 p0 = *(const float4*)&Ps[(ty*4+0)*68 + kc];
            float4 p1 = *(const float4*)&Ps[(ty*4+1)*68 + kc];
            float4 p2 = *(const float4*)&Ps[(ty*4+2)*68 + kc];
            float4 p3 = *(const float4*)&Ps[(ty*4+3)*68 + kc];
            float4 v0 = *(const float4*)&Vs[(kc+0)*68 + tx*4];
            float4 v1 = *(const float4*)&Vs[(kc+1)*68 + tx*4];
            float4 v2 = *(const float4*)&Vs[(kc+2)*68 + tx*4];
            float4 v3 = *(const float4*)&Vs[(kc+3)*68 + tx*4];
            O[0][0] += p0.x*v0.x + p0.y*v1.x + p0.z*v2.x + p0.w*v3.x;
            O[0][1] += p0.x*v0.y + p0.y*v1.y + p0.z*v2.y + p0.w*v3.y;
            O[0][2] += p0.x*v0.z + p0.y*v1.z + p0.z*v2.z + p0.w*v3.z;
            O[0][3] += p0.x*v0.w + p0.y*v1.w + p0.z*v2.w + p0.w*v3.w;
            O[1][0] += p1.x*v0.x + p1.y*v1.x + p1.z*v2.x + p1.w*v3.x;
            O[1][1] += p1.x*v0.y + p1.y*v1.y + p1.z*v2.y + p1.w*v3.y;
            O[1][2] += p1.x*v0.z + p1.y*v1.z + p1.z*v2.z + p1.w*v3.z;
            O[1][3] += p1.x*v0.w + p1.y*v1.w + p1.z*v2.w + p1.w*v3.w;
            O[2][0] += p2.x*v0.x + p2.y*v1.x + p2.z*v2.x + p2.w*v3.x;
            O[2][1] += p2.x*v0.y + p2.y*v1.y + p2.z*v2.y + p2.w*v3.y;
            O[2][2] += p2.x*v0.z + p2.y*v1.z + p2.z*v2.z + p2.w*v3.z;
            O[2][3] += p2.x*v0.w + p2.y*v1.w + p2.z*v2.w + p2.w*v3.w;
            O[3][0] += p3.x*v0.x + p3.y*v1.x + p3.z*v2.x + p3.w*v3.x;
            O[3][1] += p3.x*v0.y + p3.y*v1.y + p3.z*v2.y + p3.w*v3.y;
            O[3][2] += p3.x*v0.z + p3.y*v1.z + p3.z*v2.z + p3.w*v3.z;
            O[3][3] += p3.x*v0.w + p3.y*v1.w + p3.z*v2.w + p3.w*v3.w;
        }
        __syncthreads();
    }

    // epilogue: normalize and store token-major
    #pragma unroll
    for (int i = 0; i < 4; i++) {
        float inv = 1.f / l_i[i];
        float4 r;
        r.x = O[i][0]*inv; r.y = O[i][1]*inv; r.z = O[i][2]*inv; r.w = O[i][3]*inv;
        *(float4*)&g_o[(size_t)(q0 + ty*4 + i) * CIN + h * HD + tx * 4] = r;
    }
}

// ---------------------------------------------------------------------------
// Kernel 3: output projection.
// out[o][t] = sum_c p_w[o][c] * g_o[t][c] + p_b[o]
// grid: (64 token-tiles, 8 o-tiles)
// ---------------------------------------------------------------------------
__global__ __launch_bounds__(256)
void out_proj_kernel(const float* __restrict__ pw, const float* __restrict__ pb,
                     float* __restrict__ out)
{
    __shared__ float Ws[32][68];   // Ws[k][o]
    __shared__ float Ts[32][68];   // Ts[k][t]

    const int tid = threadIdx.x;
    const int tx = tid & 15, ty = tid >> 4;
    const int t0 = blockIdx.x * 64;
    const int o0 = blockIdx.y * 64;

    float acc[4][4] = {};
    const int rr = tid >> 2, kc = (tid & 3) * 8;

    for (int k0 = 0; k0 < CIN; k0 += 32) {
        {
            const float* wp = pw + (size_t)(o0 + rr) * CIN + k0 + kc;
            float4 w0 = *(const float4*)wp;
            float4 w1 = *(const float4*)(wp + 4);
            Ws[kc+0][rr] = w0.x; Ws[kc+1][rr] = w0.y; Ws[kc+2][rr] = w0.z; Ws[kc+3][rr] = w0.w;
            Ws[kc+4][rr] = w1.x; Ws[kc+5][rr] = w1.y; Ws[kc+6][rr] = w1.z; Ws[kc+7][rr] = w1.w;
        }
        {
            const float* tp = g_o + (size_t)(t0 + rr) * CIN + k0 + kc;
            float4 u0 = *(const float4*)tp;
            float4 u1 = *(const float4*)(tp + 4);
            Ts[kc+0][rr] = u0.x; Ts[kc+1][rr] = u0.y; Ts[kc+2][rr] = u0.z; Ts[kc+3][rr] = u0.w;
            Ts[kc+4][rr] = u1.x; Ts[kc+5][rr] = u1.y; Ts[kc+6][rr] = u1.z; Ts[kc+7][rr] = u1.w;
        }
        __syncthreads();
        #pragma unroll
        for (int k = 0; k < 32; k++) {
            float4 ov = *(const float4*)&Ws[k][ty * 4];   // o values (rows i)
            float4 tv = *(const float4*)&Ts[k][tx * 4];   // t values (cols j)
            acc[0][0] += ov.x*tv.x; acc[0][1] += ov.x*tv.y; acc[0][2] += ov.x*tv.z; acc[0][3] += ov.x*tv.w;
            acc[1][0] += ov.y*tv.x; acc[1][1] += ov.y*tv.y; acc[1][2] += ov.y*tv.z; acc[1][3] += ov.y*tv.w;
            acc[2][0] += ov.z*tv.x; acc[2][1] += ov.z*tv.y; acc[2][2] += ov.z*tv.z; acc[2][3] += ov.z*tv.w;
            acc[3][0] += ov.w*tv.x; acc[3][1] += ov.w*tv.y; acc[3][2] += ov.w*tv.z; acc[3][3] += ov.w*tv.w;
        }
        __syncthreads();
    }

    #pragma unroll
    for (int i = 0; i < 4; i++) {
        float bias = pb[o0 + ty * 4 + i];
        float4 r;
        r.x = acc[i][0] + bias; r.y = acc[i][1] + bias;
        r.z = acc[i][2] + bias; r.w = acc[i][3] + bias;
        *(float4*)&out[(size_t)(o0 + ty * 4 + i) * NTOK + t0 + tx * 4] = r;
    }
}

// ---------------------------------------------------------------------------
extern "C" void kernel_launch(void* const* d_in, const int* in_sizes, int n_in,
                              void* d_out, int out_size)
{
    (void)in_sizes; (void)n_in; (void)out_size;
    const float* x   = (const float*)d_in[0];
    const float* qw  = (const float*)d_in[1];
    const float* qb  = (const float*)d_in[2];
    const float* kw  = (const float*)d_in[3];
    const float* kb  = (const float*)d_in[4];
    const float* vw  = (const float*)d_in[5];
    const float* vb  = (const float*)d_in[6];
    const float* pw  = (const float*)d_in[7];
    const float* pb  = (const float*)d_in[8];
    const float* lqw = (const float*)d_in[9];
    float* out = (float*)d_out;

    const int attn_smem = 4 * 64 * 68 * (int)sizeof(float);  // 69632 B
    cudaFuncSetAttribute(attn_kernel, cudaFuncAttributeMaxDynamicSharedMemorySize, attn_smem);

    qkv_proj_kernel<<<dim3(NTOK / 64, 24), 256>>>(x, qw, qb, kw, kb, vw, vb);
    attn_kernel<<<dim3(NTOK / 64, HEADS), 256, attn_smem>>>(lqw);
    out_proj_kernel<<<dim3(NTOK / 64, CIN / 64), 256>>>(pw, pb, out);
}

// round 3
// speedup vs baseline: 1.7281x; 1.7281x over previous
#include <cuda_runtime.h>
#include <cstdint>

// ---------------------------------------------------------------------------
// AttentionS2: B=1, C=512, HEADS=8, hd=64, tokens HW=4096
// ---------------------------------------------------------------------------

#define NTOK 4096
#define CIN  512
#define HEADS 8
#define HD 64

__device__ float g_q[NTOK * CIN];
__device__ float g_k[NTOK * CIN];
__device__ float g_v[NTOK * CIN];
__device__ float g_o[NTOK * CIN];

// fast exp on the FMA/ALU pipes (avoids MUFU bottleneck).
// exp(x) = 2^(x*log2e); split int/frac via magic constant; deg-5 poly for 2^f.
__device__ __forceinline__ float fast_exp(float x) {
    x = fmaxf(x, -87.0f);                       // avoid exponent wrap
    float z = x * 1.4426950408889634f;
    float r = z + 12582912.0f;                  // 1.5*2^23: round-to-nearest int
    int   n = __float_as_int(r) - 0x4B400000;   // integer part
    float f = z - (r - 12582912.0f);            // frac in [-0.5, 0.5]
    float p = 1.3333558e-4f;
    p = fmaf(p, f, 1.3336425e-3f);
    p = fmaf(p, f, 9.6181291e-3f);
    p = fmaf(p, f, 5.5504109e-2f);
    p = fmaf(p, f, 2.4022651e-1f);
    p = fmaf(p, f, 6.9314718e-1f);
    p = fmaf(p, f, 1.0f);
    return __int_as_float(__float_as_int(p) + (n << 23));
}

// ---------------------------------------------------------------------------
// Kernel 1: fused QKV projection. out[t][o] = sum_i x[i][t]*w[o][i] + b[o]
// 128x128 tile, k-step 16, 256 threads, 8x8 per thread (1 B/FMA balanced).
// ---------------------------------------------------------------------------
__global__ __launch_bounds__(256)
void qkv_proj_kernel(const float* __restrict__ x,
                     const float* __restrict__ qw, const float* __restrict__ qb,
                     const float* __restrict__ kw, const float* __restrict__ kb,
                     const float* __restrict__ vw, const float* __restrict__ vb)
{
    __shared__ float As[16][128];   // As[k][t]
    __shared__ float Bs[16][132];   // Bs[k][o]

    const int tid = threadIdx.x;
    const int tx = tid & 15, ty = tid >> 4;
    const int t0 = blockIdx.x * 128;
    const int nt = blockIdx.y;           // 0..11
    const int which = nt >> 2;           // 0=q 1=k 2=v
    const int o0 = (nt & 3) * 128;

    const float* w   = (which == 0) ? qw : (which == 1) ? kw : vw;
    const float* bia = (which == 0) ? qb : (which == 1) ? kb : vb;
    float*       out = (which == 0) ? g_q : (which == 1) ? g_k : g_v;

    float acc[8][8] = {};

    for (int k0 = 0; k0 < CIN; k0 += 16) {
        #pragma unroll
        for (int u = 0; u < 2; u++) {
            int f = tid + u * 256;
            int ak = f >> 5, at = (f & 31) * 4;
            *(float4*)&As[ak][at] = *(const float4*)&x[(size_t)(k0 + ak) * NTOK + t0 + at];
            int bo = f >> 2, bk = (f & 3) * 4;
            float4 bv = *(const float4*)&w[(size_t)(o0 + bo) * CIN + k0 + bk];
            Bs[bk+0][bo] = bv.x; Bs[bk+1][bo] = bv.y;
            Bs[bk+2][bo] = bv.z; Bs[bk+3][bo] = bv.w;
        }
        __syncthreads();
        #pragma unroll
        for (int k = 0; k < 16; k++) {
            float4 a0 = *(const float4*)&As[k][ty * 4];
            float4 a1 = *(const float4*)&As[k][64 + ty * 4];
            float4 b0 = *(const float4*)&Bs[k][tx * 4];
            float4 b1 = *(const float4*)&Bs[k][64 + tx * 4];
            float av[8] = {a0.x,a0.y,a0.z,a0.w,a1.x,a1.y,a1.z,a1.w};
            float bv[8] = {b0.x,b0.y,b0.z,b0.w,b1.x,b1.y,b1.z,b1.w};
            #pragma unroll
            for (int i = 0; i < 8; i++)
                #pragma unroll
                for (int j = 0; j < 8; j++)
                    acc[i][j] = fmaf(av[i], bv[j], acc[i][j]);
        }
        __syncthreads();
    }

    float4 bb0 = *(const float4*)&bia[o0 + tx * 4];
    float4 bb1 = *(const float4*)&bia[o0 + 64 + tx * 4];
    float bb[8] = {bb0.x,bb0.y,bb0.z,bb0.w,bb1.x,bb1.y,bb1.z,bb1.w};
    #pragma unroll
    for (int i = 0; i < 8; i++) {
        int row = t0 + ((i < 4) ? (ty * 4 + i) : (64 + ty * 4 + i - 4));
        float4 r0, r1;
        r0.x = acc[i][0] + bb[0]; r0.y = acc[i][1] + bb[1];
        r0.z = acc[i][2] + bb[2]; r0.w = acc[i][3] + bb[3];
        r1.x = acc[i][4] + bb[4]; r1.y = acc[i][5] + bb[5];
        r1.z = acc[i][6] + bb[6]; r1.w = acc[i][7] + bb[7];
        *(float4*)&out[(size_t)row * CIN + o0 + tx * 4]      = r0;
        *(float4*)&out[(size_t)row * CIN + o0 + 64 + tx * 4] = r1;
    }
}

// ---------------------------------------------------------------------------
// Kernel 2: flash attention, 128q x 128k tiles, 256 threads.
// QK phase: 16x16 threads, 8x8 microtile.  PV phase: 8x32 threads, 4x8.
// K stored d-major (transposed) in smem for conflict-free streaming.
// ---------------------------------------------------------------------------
__global__ __launch_bounds__(256, 1)
void attn_kernel(const float* __restrict__ lqw)
{
    extern __shared__ float smbuf[];
    float* Qs  = smbuf;                 // [128][68]
    float* Kst = Qs  + 128 * 68;        // [64][132]  K^T: Kst[d][key]
    float* Vs  = Kst + 64 * 132;        // [128][68]
    float* Ps  = Vs  + 128 * 68;        // [128][132]
    float* rowAlpha = Ps + 128 * 132;   // [128]
    float* rowL     = rowAlpha + 128;   // [128]

    const int tid = threadIdx.x;
    const int tx  = tid & 15, ty  = tid >> 4;   // QK mapping
    const int tx2 = tid & 7,  ty2 = tid >> 3;   // PV mapping
    const int h  = blockIdx.y;
    const int q0 = blockIdx.x * 128;

    // load Q tile (128 x 64)
    {
        int lr = tid >> 1, lc = (tid & 1) * 32;
        const float* src = g_q + (size_t)(q0 + lr) * CIN + h * HD + lc;
        #pragma unroll
        for (int u = 0; u < 8; u++)
            *(float4*)&Qs[lr * 68 + lc + u * 4] = *(const float4*)&src[u * 4];
    }

    float O[4][8] = {};
    float m_i[8], l_i[8];
    #pragma unroll
    for (int i = 0; i < 8; i++) { m_i[i] = -1e30f; l_i[i] = 0.f; }

    for (int kt = 0; kt < NTOK / 128; kt++) {
        __syncthreads();   // prev PV done with Ps/Vs; Q load done (first iter)
        // load K (transposed) and V
        {
            int lr = tid >> 1, lc = (tid & 1) * 32;
            const float* ks = g_k + (size_t)(kt * 128 + lr) * CIN + h * HD + lc;
            const float* vs = g_v + (size_t)(kt * 128 + lr) * CIN + h * HD + lc;
            #pragma unroll
            for (int u = 0; u < 8; u++) {
                float4 kv = *(const float4*)&ks[u * 4];
                Kst[(lc + u*4 + 0) * 132 + lr] = kv.x;
                Kst[(lc + u*4 + 1) * 132 + lr] = kv.y;
                Kst[(lc + u*4 + 2) * 132 + lr] = kv.z;
                Kst[(lc + u*4 + 3) * 132 + lr] = kv.w;
                *(float4*)&Vs[lr * 68 + lc + u * 4] = *(const float4*)&vs[u * 4];
            }
        }
        __syncthreads();

        // S = Q K^T : 8x8 per thread
        float s[8][8] = {};
        #pragma unroll
        for (int dd = 0; dd < HD; dd += 4) {
            float4 aq[8];
            #pragma unroll
            for (int i = 0; i < 4; i++) {
                aq[i]     = *(const float4*)&Qs[(ty * 4 + i) * 68 + dd];
                aq[4 + i] = *(const float4*)&Qs[(64 + ty * 4 + i) * 68 + dd];
            }
            float bvu[4][8];
            #pragma unroll
            for (int u = 0; u < 4; u++) {
                float4 b0 = *(const float4*)&Kst[(dd + u) * 132 + tx * 4];
                float4 b1 = *(const float4*)&Kst[(dd + u) * 132 + 64 + tx * 4];
                bvu[u][0] = b0.x; bvu[u][1] = b0.y; bvu[u][2] = b0.z; bvu[u][3] = b0.w;
                bvu[u][4] = b1.x; bvu[u][5] = b1.y; bvu[u][6] = b1.z; bvu[u][7] = b1.w;
            }
            #pragma unroll
            for (int i = 0; i < 8; i++) {
                #pragma unroll
                for (int j = 0; j < 8; j++) {
                    s[i][j] = fmaf(aq[i].x, bvu[0][j], s[i][j]);
                    s[i][j] = fmaf(aq[i].y, bvu[1][j], s[i][j]);
                    s[i][j] = fmaf(aq[i].z, bvu[2][j], s[i][j]);
                    s[i][j] = fmaf(aq[i].w, bvu[3][j], s[i][j]);
                }
            }
        }

        // online softmax (scale + log-quadrature key bias)
        float4 lb0 = *(const float4*)&lqw[kt * 128 + tx * 4];
        float4 lb1 = *(const float4*)&lqw[kt * 128 + 64 + tx * 4];
        float lb[8] = {lb0.x,lb0.y,lb0.z,lb0.w,lb1.x,lb1.y,lb1.z,lb1.w};
        #pragma unroll
        for (int i = 0; i < 8; i++) {
            float r[8];
            #pragma unroll
            for (int j = 0; j < 8; j++) r[j] = fmaf(s[i][j], 0.125f, lb[j]);
            float rmax = r[0];
            #pragma unroll
            for (int j = 1; j < 8; j++) rmax = fmaxf(rmax, r[j]);
            #pragma unroll
            for (int off = 1; off < 16; off <<= 1)
                rmax = fmaxf(rmax, __shfl_xor_sync(0xffffffffu, rmax, off));
            float mn = fmaxf(m_i[i], rmax);
            float alpha = fast_exp(m_i[i] - mn);
            m_i[i] = mn;
            float p[8]; float rs = 0.f;
            #pragma unroll
            for (int j = 0; j < 8; j++) { p[j] = fast_exp(r[j] - mn); rs += p[j]; }
            int row = (i < 4) ? (ty * 4 + i) : (64 + ty * 4 + i - 4);
            float4 pv0, pv1;
            pv0.x = p[0]; pv0.y = p[1]; pv0.z = p[2]; pv0.w = p[3];
            pv1.x = p[4]; pv1.y = p[5]; pv1.z = p[6]; pv1.w = p[7];
            *(float4*)&Ps[row * 132 + tx * 4]      = pv0;
            *(float4*)&Ps[row * 132 + 64 + tx * 4] = pv1;
            #pragma unroll
            for (int off = 1; off < 16; off <<= 1)
                rs += __shfl_xor_sync(0xffffffffu, rs, off);
            l_i[i] = fmaf(l_i[i], alpha, rs);
            if (tx == 0) rowAlpha[row] = alpha;
        }
        __syncthreads();

        // O = O*alpha + P V   (PV mapping: 4 rows x 8 d-cols per thread)
        {
            float al[4];
            #pragma unroll
            for (int j = 0; j < 4; j++) al[j] = rowAlpha[ty2 * 4 + j];
            #pragma unroll
            for (int j = 0; j < 4; j++)
                #pragma unroll
                for (int c = 0; c < 8; c++) O[j][c] *= al[j];

            #pragma unroll 4
            for (int kc = 0; kc < 128; kc += 4) {
                float4 pq[4];
                #pragma unroll
                for (int j = 0; j < 4; j++)
                    pq[j] = *(const float4*)&Ps[(ty2 * 4 + j) * 132 + kc];
                float vv[4][8];
                #pragma unroll
                for (int u = 0; u < 4; u++) {
                    float4 v0 = *(const float4*)&Vs[(kc + u) * 68 + tx2 * 4];
                    float4 v1 = *(const float4*)&Vs[(kc + u) * 68 + 32 + tx2 * 4];
                    vv[u][0] = v0.x; vv[u][1] = v0.y; vv[u][2] = v0.z; vv[u][3] = v0.w;
                    vv[u][4] = v1.x; vv[u][5] = v1.y; vv[u][6] = v1.z; vv[u][7] = v1.w;
                }
                #pragma unroll
                for (int j = 0; j < 4; j++) {
                    #pragma unroll
                    for (int c = 0; c < 8; c++) {
                        O[j][c] = fmaf(pq[j].x, vv[0][c], O[j][c]);
                        O[j][c] = fmaf(pq[j].y, vv[1][c], O[j][c]);
                        O[j][c] = fmaf(pq[j].z, vv[2][c], O[j][c]);
                        O[j][c] = fmaf(pq[j].w, vv[3][c], O[j][c]);
                    }
                }
            }
        }
    }

    // publish l, then normalize + store
    if (tx == 0) {
        #pragma unroll
        for (int i = 0; i < 8; i++) {
            int row = (i < 4) ? (ty * 4 + i) : (64 + ty * 4 + i - 4);
            rowL[row] = l_i[i];
        }
    }
    __syncthreads();
    #pragma unroll
    for (int j = 0; j < 4; j++) {
        float inv = 1.0f / rowL[ty2 * 4 + j];
        size_t base = (size_t)(q0 + ty2 * 4 + j) * CIN + h * HD;
        float4 o0v, o1v;
        o0v.x = O[j][0]*inv; o0v.y = O[j][1]*inv; o0v.z = O[j][2]*inv; o0v.w = O[j][3]*inv;
        o1v.x = O[j][4]*inv; o1v.y = O[j][5]*inv; o1v.z = O[j][6]*inv; o1v.w = O[j][7]*inv;
        *(float4*)&g_o[base + tx2 * 4]      = o0v;
        *(float4*)&g_o[base + 32 + tx2 * 4] = o1v;
    }
}

// ---------------------------------------------------------------------------
// Kernel 3: output projection. out[o][t] = sum_c pw[o][c]*g_o[t][c] + pb[o]
// 128x128 tile, k-step 16, 8x8 per thread. Both operands transpose-loaded.
// ---------------------------------------------------------------------------
__global__ __launch_bounds__(256)
void out_proj_kernel(const float* __restrict__ pw, const float* __restrict__ pb,
                     float* __restrict__ out)
{
    __shared__ float As[16][132];   // As[c][o]
    __shared__ float Bs[16][132];   // Bs[c][t]

    const int tid = threadIdx.x;
    const int tx = tid & 15, ty = tid >> 4;
    const int t0 = blockIdx.x * 128;
    const int o0 = blockIdx.y * 128;

    float acc[8][8] = {};

    for (int k0 = 0; k0 < CIN; k0 += 16) {
        #pragma unroll
        for (int u = 0; u < 2; u++) {
            int f = tid + u * 256;
            int ro = f >> 2, kq = (f & 3) * 4;
            float4 av = *(const float4*)&pw[(size_t)(o0 + ro) * CIN + k0 + kq];
            As[kq+0][ro] = av.x; As[kq+1][ro] = av.y;
            As[kq+2][ro] = av.z; As[kq+3][ro] = av.w;
            float4 bv = *(const float4*)&g_o[(size_t)(t0 + ro) * CIN + k0 + kq];
            Bs[kq+0][ro] = bv.x; Bs[kq+1][ro] = bv.y;
            Bs[kq+2][ro] = bv.z; Bs[kq+3][ro] = bv.w;
        }
        __syncthreads();
        #pragma unroll
        for (int k = 0; k < 16; k++) {
            float4 a0 = *(const float4*)&As[k][ty * 4];
            float4 a1 = *(const float4*)&As[k][64 + ty * 4];
            float4 b0 = *(const float4*)&Bs[k][tx * 4];
            float4 b1 = *(const float4*)&Bs[k][64 + tx * 4];
            float av[8] = {a0.x,a0.y,a0.z,a0.w,a1.x,a1.y,a1.z,a1.w};
            float bv[8] = {b0.x,b0.y,b0.z,b0.w,b1.x,b1.y,b1.z,b1.w};
            #pragma unroll
            for (int i = 0; i < 8; i++)
                #pragma unroll
                for (int j = 0; j < 8; j++)
                    acc[i][j] = fmaf(av[i], bv[j], acc[i][j]);
        }
        __syncthreads();
    }

    #pragma unroll
    for (int i = 0; i < 8; i++) {
        int orow = o0 + ((i < 4) ? (ty * 4 + i) : (64 + ty * 4 + i - 4));
        float bias = pb[orow];
        float4 r0, r1;
        r0.x = acc[i][0] + bias; r0.y = acc[i][1] + bias;
        r0.z = acc[i][2] + bias; r0.w = acc[i][3] + bias;
        r1.x = acc[i][4] + bias; r1.y = acc[i][5] + bias;
        r1.z = acc[i][6] + bias; r1.w = acc[i][7] + bias;
        *(float4*)&out[(size_t)orow * NTOK + t0 + tx * 4]      = r0;
        *(float4*)&out[(size_t)orow * NTOK + t0 + 64 + tx * 4] = r1;
    }
}

// ---------------------------------------------------------------------------
extern "C" void kernel_launch(void* const* d_in, const int* in_sizes, int n_in,
                              void* d_out, int out_size)
{
    (void)in_sizes; (void)n_in; (void)out_size;
    const float* x   = (const float*)d_in[0];
    const float* qw  = (const float*)d_in[1];
    const float* qb  = (const float*)d_in[2];
    const float* kw  = (const float*)d_in[3];
    const float* kb  = (const float*)d_in[4];
    const float* vw  = (const float*)d_in[5];
    const float* vb  = (const float*)d_in[6];
    const float* pw  = (const float*)d_in[7];
    const float* pb  = (const float*)d_in[8];
    const float* lqw = (const float*)d_in[9];
    float* out = (float*)d_out;

    // attn smem: Qs 128*68 + Kst 64*132 + Vs 128*68 + Ps 128*132 + 256 stats
    const int attn_smem = (128*68 + 64*132 + 128*68 + 128*132 + 256) * (int)sizeof(float);
    cudaFuncSetAttribute(attn_kernel, cudaFuncAttributeMaxDynamicSharedMemorySize, attn_smem);

    qkv_proj_kernel<<<dim3(NTOK / 128, 12), 256>>>(x, qw, qb, kw, kb, vw, vb);
    attn_kernel<<<dim3(NTOK / 128, HEADS), 256, attn_smem>>>(lqw);
    out_proj_kernel<<<dim3(NTOK / 128, CIN / 128), 256>>>(pw, pb, out);
}

// round 4
// speedup vs baseline: 3.3643x; 1.9468x over previous
#include <cuda_runtime.h>
#include <cuda_bf16.h>
#include <cstdint>

// ---------------------------------------------------------------------------
// AttentionS2: B=1, C=512, HEADS=8, hd=64, tokens HW=4096
// Attention GEMMs on tensor cores (bf16 hi/lo 3-term split, fp32 accum).
// ---------------------------------------------------------------------------

#define NTOK 4096
#define CIN  512
#define HEADS 8
#define HD 64

// bf16 hi/lo splits of projections (written by qkv_proj)
__device__ __nv_bfloat16 g_qhi[NTOK * CIN], g_qlo[NTOK * CIN];   // [tok][chan]
__device__ __nv_bfloat16 g_khi[NTOK * CIN], g_klo[NTOK * CIN];   // [tok][chan]
__device__ __nv_bfloat16 g_vhi[CIN * NTOK], g_vlo[CIN * NTOK];   // [chan][tok] (transposed)
__device__ float g_o[NTOK * CIN];

// fast exp on FMA/ALU pipes (avoids MUFU bottleneck)
__device__ __forceinline__ float fast_exp(float x) {
    x = fmaxf(x, -87.0f);
    float z = x * 1.4426950408889634f;
    float r = z + 12582912.0f;
    int   n = __float_as_int(r) - 0x4B400000;
    float f = z - (r - 12582912.0f);
    float p = 1.3333558e-4f;
    p = fmaf(p, f, 1.3336425e-3f);
    p = fmaf(p, f, 9.6181291e-3f);
    p = fmaf(p, f, 5.5504109e-2f);
    p = fmaf(p, f, 2.4022651e-1f);
    p = fmaf(p, f, 6.9314718e-1f);
    p = fmaf(p, f, 1.0f);
    return __int_as_float(__float_as_int(p) + (n << 23));
}

// split (v0,v1) into packed bf16x2 hi and lo (lo = residual), low half = v0
__device__ __forceinline__ void split2(float v0, float v1, uint32_t& hi, uint32_t& lo) {
    uint32_t h;
    asm("cvt.rn.bf16x2.f32 %0, %1, %2;" : "=r"(h) : "f"(v1), "f"(v0));
    float h0 = __uint_as_float(h << 16);
    float h1 = __uint_as_float(h & 0xFFFF0000u);
    asm("cvt.rn.bf16x2.f32 %0, %1, %2;" : "=r"(lo) : "f"(v1 - h1), "f"(v0 - h0));
    hi = h;
}

__device__ __forceinline__ void mma_bf16(float* c, const uint32_t* a, uint32_t b0, uint32_t b1) {
    asm volatile(
        "mma.sync.aligned.m16n8k16.row.col.f32.bf16.bf16.f32 "
        "{%0,%1,%2,%3},{%4,%5,%6,%7},{%8,%9},{%0,%1,%2,%3};"
        : "+f"(c[0]), "+f"(c[1]), "+f"(c[2]), "+f"(c[3])
        : "r"(a[0]), "r"(a[1]), "r"(a[2]), "r"(a[3]), "r"(b0), "r"(b1));
}

// ---------------------------------------------------------------------------
// Kernel 1: fused QKV projection, bf16 hi/lo output.
// 128x128 tile, k-step 16, 256 threads, 8x8 per thread.
// ---------------------------------------------------------------------------
__global__ __launch_bounds__(256)
void qkv_proj_kernel(const float* __restrict__ x,
                     const float* __restrict__ qw, const float* __restrict__ qb,
                     const float* __restrict__ kw, const float* __restrict__ kb,
                     const float* __restrict__ vw, const float* __restrict__ vb)
{
    __shared__ float As[16][128];
    __shared__ float Bs[16][132];

    const int tid = threadIdx.x;
    const int tx = tid & 15, ty = tid >> 4;
    const int t0 = blockIdx.x * 128;
    const int nt = blockIdx.y;           // 0..11
    const int which = nt >> 2;           // 0=q 1=k 2=v
    const int o0 = (nt & 3) * 128;

    const float* w   = (which == 0) ? qw : (which == 1) ? kw : vw;
    const float* bia = (which == 0) ? qb : (which == 1) ? kb : vb;

    float acc[8][8] = {};

    for (int k0 = 0; k0 < CIN; k0 += 16) {
        #pragma unroll
        for (int u = 0; u < 2; u++) {
            int f = tid + u * 256;
            int ak = f >> 5, at = (f & 31) * 4;
            *(float4*)&As[ak][at] = *(const float4*)&x[(size_t)(k0 + ak) * NTOK + t0 + at];
            int bo = f >> 2, bk = (f & 3) * 4;
            float4 bv = *(const float4*)&w[(size_t)(o0 + bo) * CIN + k0 + bk];
            Bs[bk+0][bo] = bv.x; Bs[bk+1][bo] = bv.y;
            Bs[bk+2][bo] = bv.z; Bs[bk+3][bo] = bv.w;
        }
        __syncthreads();
        #pragma unroll
        for (int k = 0; k < 16; k++) {
            float4 a0 = *(const float4*)&As[k][ty * 4];
            float4 a1 = *(const float4*)&As[k][64 + ty * 4];
            float4 b0 = *(const float4*)&Bs[k][tx * 4];
            float4 b1 = *(const float4*)&Bs[k][64 + tx * 4];
            float av[8] = {a0.x,a0.y,a0.z,a0.w,a1.x,a1.y,a1.z,a1.w};
            float bv[8] = {b0.x,b0.y,b0.z,b0.w,b1.x,b1.y,b1.z,b1.w};
            #pragma unroll
            for (int i = 0; i < 8; i++)
                #pragma unroll
                for (int j = 0; j < 8; j++)
                    acc[i][j] = fmaf(av[i], bv[j], acc[i][j]);
        }
        __syncthreads();
    }

    float4 bb0 = *(const float4*)&bia[o0 + tx * 4];
    float4 bb1 = *(const float4*)&bia[o0 + 64 + tx * 4];
    float bb[8] = {bb0.x,bb0.y,bb0.z,bb0.w,bb1.x,bb1.y,bb1.z,bb1.w};

    if (which < 2) {
        uint16_t* ohi = (uint16_t*)((which == 0) ? g_qhi : g_khi);
        uint16_t* olo = (uint16_t*)((which == 0) ? g_qlo : g_klo);
        #pragma unroll
        for (int i = 0; i < 8; i++) {
            int row = t0 + ((i < 4) ? (ty * 4 + i) : (64 + ty * 4 + i - 4));
            uint32_t h0, l0, h1, l1;
            split2(acc[i][0] + bb[0], acc[i][1] + bb[1], h0, l0);
            split2(acc[i][2] + bb[2], acc[i][3] + bb[3], h1, l1);
            uint2 uh; uh.x = h0; uh.y = h1;
            uint2 ul; ul.x = l0; ul.y = l1;
            *(uint2*)(ohi + (size_t)row * CIN + o0 + tx * 4) = uh;
            *(uint2*)(olo + (size_t)row * CIN + o0 + tx * 4) = ul;
            split2(acc[i][4] + bb[4], acc[i][5] + bb[5], h0, l0);
            split2(acc[i][6] + bb[6], acc[i][7] + bb[7], h1, l1);
            uh.x = h0; uh.y = h1; ul.x = l0; ul.y = l1;
            *(uint2*)(ohi + (size_t)row * CIN + o0 + 64 + tx * 4) = uh;
            *(uint2*)(olo + (size_t)row * CIN + o0 + 64 + tx * 4) = ul;
        }
    } else {
        // V: store transposed [chan][tok]
        uint16_t* ohi = (uint16_t*)g_vhi;
        uint16_t* olo = (uint16_t*)g_vlo;
        #pragma unroll
        for (int j = 0; j < 8; j++) {
            int col = o0 + ((j < 4) ? (tx * 4 + j) : (64 + tx * 4 + j - 4));
            float b = bb[j];
            uint32_t h0, l0, h1, l1;
            split2(acc[0][j] + b, acc[1][j] + b, h0, l0);
            split2(acc[2][j] + b, acc[3][j] + b, h1, l1);
            uint2 uh; uh.x = h0; uh.y = h1;
            uint2 ul; ul.x = l0; ul.y = l1;
            *(uint2*)(ohi + (size_t)col * NTOK + t0 + ty * 4) = uh;
            *(uint2*)(olo + (size_t)col * NTOK + t0 + ty * 4) = ul;
            split2(acc[4][j] + b, acc[5][j] + b, h0, l0);
            split2(acc[6][j] + b, acc[7][j] + b, h1, l1);
            uh.x = h0; uh.y = h1; ul.x = l0; ul.y = l1;
            *(uint2*)(ohi + (size_t)col * NTOK + t0 + 64 + ty * 4) = uh;
            *(uint2*)(olo + (size_t)col * NTOK + t0 + 64 + ty * 4) = ul;
        }
    }
}

// ---------------------------------------------------------------------------
// Kernel 2: flash attention on tensor cores (mma.sync bf16, hi/lo split).
// 256 thr = 8 warps; warp w owns q-rows [w*16, w*16+16). 128-key tiles.
// smem strides: Q/K rows 72 bf16, Vt rows 136 bf16 (conflict-free frags).
// ---------------------------------------------------------------------------
__global__ __launch_bounds__(256, 1)
void attn_kernel(const float* __restrict__ lqw)
{
    extern __shared__ uint16_t sm16[];
    uint16_t* qhi  = sm16;                 // 128*72
    uint16_t* qlo  = qhi + 128 * 72;
    uint16_t* khi  = qlo + 128 * 72;
    uint16_t* klo  = khi + 128 * 72;
    uint16_t* vthi = klo + 128 * 72;       // 64*136  Vt[d][key]
    uint16_t* vtlo = vthi + 64 * 136;
    float*    lqs  = (float*)(vtlo + 64 * 136);  // 128 floats

    const int tid  = threadIdx.x;
    const int w    = tid >> 5, lane = tid & 31;
    const int g    = lane >> 2, tig = lane & 3;
    const int h    = blockIdx.y;
    const int q0   = blockIdx.x * 128;

    // stage Q (hi+lo): 128 rows x 8 uint4
    for (int idx = tid; idx < 1024; idx += 256) {
        int r = idx >> 3, c4 = idx & 7;
        *(uint4*)(qhi + r * 72 + c4 * 8) =
            *((const uint4*)((const uint16_t*)g_qhi + (size_t)(q0 + r) * CIN + h * HD) + c4);
        *(uint4*)(qlo + r * 72 + c4 * 8) =
            *((const uint4*)((const uint16_t*)g_qlo + (size_t)(q0 + r) * CIN + h * HD) + c4);
    }
    __syncthreads();

    // load Q A-fragments into registers (4 k-steps x 4 regs, hi+lo)
    uint32_t qahi[4][4], qalo[4][4];
    {
        const uint16_t* qr = qhi + (w * 16 + g) * 72 + 2 * tig;
        const uint16_t* ql = qlo + (w * 16 + g) * 72 + 2 * tig;
        #pragma unroll
        for (int ks = 0; ks < 4; ks++) {
            qahi[ks][0] = *(const uint32_t*)(qr + ks * 16);
            qahi[ks][1] = *(const uint32_t*)(qr + 8 * 72 + ks * 16);
            qahi[ks][2] = *(const uint32_t*)(qr + ks * 16 + 8);
            qahi[ks][3] = *(const uint32_t*)(qr + 8 * 72 + ks * 16 + 8);
            qalo[ks][0] = *(const uint32_t*)(ql + ks * 16);
            qalo[ks][1] = *(const uint32_t*)(ql + 8 * 72 + ks * 16);
            qalo[ks][2] = *(const uint32_t*)(ql + ks * 16 + 8);
            qalo[ks][3] = *(const uint32_t*)(ql + 8 * 72 + ks * 16 + 8);
        }
    }

    float O[8][4] = {};
    float m0 = -1e30f, m1 = -1e30f, l0 = 0.f, l1 = 0.f;

    #pragma unroll 1
    for (int kt = 0; kt < NTOK / 128; kt++) {
        __syncthreads();
        // stage K (hi+lo) and Vt (hi+lo)
        for (int idx = tid; idx < 1024; idx += 256) {
            int r = idx >> 3, c4 = idx & 7;
            *(uint4*)(khi + r * 72 + c4 * 8) =
                *((const uint4*)((const uint16_t*)g_khi + (size_t)(kt * 128 + r) * CIN + h * HD) + c4);
            *(uint4*)(klo + r * 72 + c4 * 8) =
                *((const uint4*)((const uint16_t*)g_klo + (size_t)(kt * 128 + r) * CIN + h * HD) + c4);
            int d = idx >> 4, e4 = idx & 15;
            *(uint4*)(vthi + d * 136 + e4 * 8) =
                *((const uint4*)((const uint16_t*)g_vhi + (size_t)(h * HD + d) * NTOK + kt * 128) + e4);
            *(uint4*)(vtlo + d * 136 + e4 * 8) =
                *((const uint4*)((const uint16_t*)g_vlo + (size_t)(h * HD + d) * NTOK + kt * 128) + e4);
        }
        if (tid < 128) lqs[tid] = lqw[kt * 128 + tid];
        __syncthreads();

        // ---- S = Q K^T : 16 n-chunks x 4 k-steps x 3 split terms ----
        float s[16][4];
        #pragma unroll
        for (int n = 0; n < 16; n++) { s[n][0]=0.f; s[n][1]=0.f; s[n][2]=0.f; s[n][3]=0.f; }
        {
            const uint16_t* kbh = khi + g * 72 + 2 * tig;
            const uint16_t* kbl = klo + g * 72 + 2 * tig;
            #pragma unroll
            for (int n = 0; n < 16; n++) {
                #pragma unroll
                for (int ks = 0; ks < 4; ks++) {
                    uint32_t bh0 = *(const uint32_t*)(kbh + n * 576 + ks * 16);
                    uint32_t bh1 = *(const uint32_t*)(kbh + n * 576 + ks * 16 + 8);
                    uint32_t bl0 = *(const uint32_t*)(kbl + n * 576 + ks * 16);
                    uint32_t bl1 = *(const uint32_t*)(kbl + n * 576 + ks * 16 + 8);
                    mma_bf16(s[n], qahi[ks], bh0, bh1);
                    mma_bf16(s[n], qahi[ks], bl0, bl1);
                    mma_bf16(s[n], qalo[ks], bh0, bh1);
                }
            }
        }

        // ---- online softmax in registers ----
        float mx0 = -1e30f, mx1 = -1e30f;
        #pragma unroll
        for (int n = 0; n < 16; n++) {
            float2 lw = *(const float2*)&lqs[n * 8 + 2 * tig];
            s[n][0] = fmaf(s[n][0], 0.125f, lw.x);
            s[n][1] = fmaf(s[n][1], 0.125f, lw.y);
            s[n][2] = fmaf(s[n][2], 0.125f, lw.x);
            s[n][3] = fmaf(s[n][3], 0.125f, lw.y);
            mx0 = fmaxf(mx0, fmaxf(s[n][0], s[n][1]));
            mx1 = fmaxf(mx1, fmaxf(s[n][2], s[n][3]));
        }
        mx0 = fmaxf(mx0, __shfl_xor_sync(0xffffffffu, mx0, 1));
        mx0 = fmaxf(mx0, __shfl_xor_sync(0xffffffffu, mx0, 2));
        mx1 = fmaxf(mx1, __shfl_xor_sync(0xffffffffu, mx1, 1));
        mx1 = fmaxf(mx1, __shfl_xor_sync(0xffffffffu, mx1, 2));

        float mn0 = fmaxf(m0, mx0), mn1 = fmaxf(m1, mx1);
        float al0 = fast_exp(m0 - mn0), al1 = fast_exp(m1 - mn1);
        m0 = mn0; m1 = mn1;

        float sum0 = 0.f, sum1 = 0.f;
        #pragma unroll
        for (int n = 0; n < 16; n++) {
            s[n][0] = fast_exp(s[n][0] - mn0);
            s[n][1] = fast_exp(s[n][1] - mn0);
            s[n][2] = fast_exp(s[n][2] - mn1);
            s[n][3] = fast_exp(s[n][3] - mn1);
            sum0 += s[n][0] + s[n][1];
            sum1 += s[n][2] + s[n][3];
        }
        sum0 += __shfl_xor_sync(0xffffffffu, sum0, 1);
        sum0 += __shfl_xor_sync(0xffffffffu, sum0, 2);
        sum1 += __shfl_xor_sync(0xffffffffu, sum1, 1);
        sum1 += __shfl_xor_sync(0xffffffffu, sum1, 2);
        l0 = fmaf(l0, al0, sum0);
        l1 = fmaf(l1, al1, sum1);

        #pragma unroll
        for (int nd = 0; nd < 8; nd++) {
            O[nd][0] *= al0; O[nd][1] *= al0;
            O[nd][2] *= al1; O[nd][3] *= al1;
        }

        // ---- O += P V : P from S regs (C-frag == A-frag), V from smem ----
        {
            const uint16_t* vbh = vthi + g * 136 + 2 * tig;
            const uint16_t* vbl = vtlo + g * 136 + 2 * tig;
            #pragma unroll
            for (int c = 0; c < 8; c++) {
                uint32_t ah[4], al[4];
                split2(s[2*c][0],   s[2*c][1],   ah[0], al[0]);
                split2(s[2*c][2],   s[2*c][3],   ah[1], al[1]);
                split2(s[2*c+1][0], s[2*c+1][1], ah[2], al[2]);
                split2(s[2*c+1][2], s[2*c+1][3], ah[3], al[3]);
                #pragma unroll
                for (int nd = 0; nd < 8; nd++) {
                    uint32_t bh0 = *(const uint32_t*)(vbh + nd * 1088 + c * 16);
                    uint32_t bh1 = *(const uint32_t*)(vbh + nd * 1088 + c * 16 + 8);
                    uint32_t bl0 = *(const uint32_t*)(vbl + nd * 1088 + c * 16);
                    uint32_t bl1 = *(const uint32_t*)(vbl + nd * 1088 + c * 16 + 8);
                    mma_bf16(O[nd], ah, bh0, bh1);
                    mma_bf16(O[nd], ah, bl0, bl1);
                    mma_bf16(O[nd], al, bh0, bh1);
                }
            }
        }
    }

    // epilogue: normalize, write fp32 token-major
    float i0 = 1.0f / l0, i1 = 1.0f / l1;
    #pragma unroll
    for (int nd = 0; nd < 8; nd++) {
        float2 w0; w0.x = O[nd][0] * i0; w0.y = O[nd][1] * i0;
        float2 w1; w1.x = O[nd][2] * i1; w1.y = O[nd][3] * i1;
        *(float2*)&g_o[(size_t)(q0 + w * 16 + g)     * CIN + h * HD + nd * 8 + 2 * tig] = w0;
        *(float2*)&g_o[(size_t)(q0 + w * 16 + g + 8) * CIN + h * HD + nd * 8 + 2 * tig] = w1;
    }
}

// ---------------------------------------------------------------------------
// Kernel 3: output projection (fp32 SIMT).
// ---------------------------------------------------------------------------
__global__ __launch_bounds__(256)
void out_proj_kernel(const float* __restrict__ pw, const float* __restrict__ pb,
                     float* __restrict__ out)
{
    __shared__ float As[16][132];
    __shared__ float Bs[16][132];

    const int tid = threadIdx.x;
    const int tx = tid & 15, ty = tid >> 4;
    const int t0 = blockIdx.x * 128;
    const int o0 = blockIdx.y * 128;

    float acc[8][8] = {};

    for (int k0 = 0; k0 < CIN; k0 += 16) {
        #pragma unroll
        for (int u = 0; u < 2; u++) {
            int f = tid + u * 256;
            int ro = f >> 2, kq = (f & 3) * 4;
            float4 av = *(const float4*)&pw[(size_t)(o0 + ro) * CIN + k0 + kq];
            As[kq+0][ro] = av.x; As[kq+1][ro] = av.y;
            As[kq+2][ro] = av.z; As[kq+3][ro] = av.w;
            float4 bv = *(const float4*)&g_o[(size_t)(t0 + ro) * CIN + k0 + kq];
            Bs[kq+0][ro] = bv.x; Bs[kq+1][ro] = bv.y;
            Bs[kq+2][ro] = bv.z; Bs[kq+3][ro] = bv.w;
        }
        __syncthreads();
        #pragma unroll
        for (int k = 0; k < 16; k++) {
            float4 a0 = *(const float4*)&As[k][ty * 4];
            float4 a1 = *(const float4*)&As[k][64 + ty * 4];
            float4 b0 = *(const float4*)&Bs[k][tx * 4];
            float4 b1 = *(const float4*)&Bs[k][64 + tx * 4];
            float av[8] = {a0.x,a0.y,a0.z,a0.w,a1.x,a1.y,a1.z,a1.w};
            float bv[8] = {b0.x,b0.y,b0.z,b0.w,b1.x,b1.y,b1.z,b1.w};
            #pragma unroll
            for (int i = 0; i < 8; i++)
                #pragma unroll
                for (int j = 0; j < 8; j++)
                    acc[i][j] = fmaf(av[i], bv[j], acc[i][j]);
        }
        __syncthreads();
    }

    #pragma unroll
    for (int i = 0; i < 8; i++) {
        int orow = o0 + ((i < 4) ? (ty * 4 + i) : (64 + ty * 4 + i - 4));
        float bias = pb[orow];
        float4 r0, r1;
        r0.x = acc[i][0] + bias; r0.y = acc[i][1] + bias;
        r0.z = acc[i][2] + bias; r0.w = acc[i][3] + bias;
        r1.x = acc[i][4] + bias; r1.y = acc[i][5] + bias;
        r1.z = acc[i][6] + bias; r1.w = acc[i][7] + bias;
        *(float4*)&out[(size_t)orow * NTOK + t0 + tx * 4]      = r0;
        *(float4*)&out[(size_t)orow * NTOK + t0 + 64 + tx * 4] = r1;
    }
}

// ---------------------------------------------------------------------------
extern "C" void kernel_launch(void* const* d_in, const int* in_sizes, int n_in,
                              void* d_out, int out_size)
{
    (void)in_sizes; (void)n_in; (void)out_size;
    const float* x   = (const float*)d_in[0];
    const float* qw  = (const float*)d_in[1];
    const float* qb  = (const float*)d_in[2];
    const float* kw  = (const float*)d_in[3];
    const float* kb  = (const float*)d_in[4];
    const float* vw  = (const float*)d_in[5];
    const float* vb  = (const float*)d_in[6];
    const float* pw  = (const float*)d_in[7];
    const float* pb  = (const float*)d_in[8];
    const float* lqw = (const float*)d_in[9];
    float* out = (float*)d_out;

    // smem: 4 x 128*72 bf16 + 2 x 64*136 bf16 + 128 f32 = 109,056 B
    const int attn_smem = (4 * 128 * 72 + 2 * 64 * 136) * 2 + 128 * 4;
    cudaFuncSetAttribute(attn_kernel, cudaFuncAttributeMaxDynamicSharedMemorySize, attn_smem);

    qkv_proj_kernel<<<dim3(NTOK / 128, 12), 256>>>(x, qw, qb, kw, kb, vw, vb);
    attn_kernel<<<dim3(NTOK / 128, HEADS), 256, attn_smem>>>(lqw);
    out_proj_kernel<<<dim3(NTOK / 128, CIN / 128), 256>>>(pw, pb, out);
}

// round 5
// speedup vs baseline: 4.2110x; 1.2517x over previous
#include <cuda_runtime.h>
#include <cuda_bf16.h>
#include <cstdint>

// ---------------------------------------------------------------------------
// AttentionS2: B=1, C=512, HEADS=8, hd=64, tokens HW=4096
// All GEMMs except out_proj on tensor cores (bf16 hi/lo 3-term, fp32 accum).
// ---------------------------------------------------------------------------

#define NTOK 4096
#define CIN  512
#define HEADS 8
#define HD 64

// bf16 hi/lo splits, all token-major [tok][chan]
__device__ __nv_bfloat16 g_qhi[NTOK * CIN], g_qlo[NTOK * CIN];
__device__ __nv_bfloat16 g_khi[NTOK * CIN], g_klo[NTOK * CIN];
__device__ __nv_bfloat16 g_vhi[NTOK * CIN], g_vlo[NTOK * CIN];
__device__ float g_o[NTOK * CIN];

// fast exp on FMA/ALU pipes (avoids MUFU bottleneck)
__device__ __forceinline__ float fast_exp(float x) {
    x = fmaxf(x, -87.0f);
    float z = x * 1.4426950408889634f;
    float r = z + 12582912.0f;
    int   n = __float_as_int(r) - 0x4B400000;
    float f = z - (r - 12582912.0f);
    float p = 1.3333558e-4f;
    p = fmaf(p, f, 1.3336425e-3f);
    p = fmaf(p, f, 9.6181291e-3f);
    p = fmaf(p, f, 5.5504109e-2f);
    p = fmaf(p, f, 2.4022651e-1f);
    p = fmaf(p, f, 6.9314718e-1f);
    p = fmaf(p, f, 1.0f);
    return __int_as_float(__float_as_int(p) + (n << 23));
}

// split (v0,v1) into packed bf16x2 hi and lo residual; low half = v0
__device__ __forceinline__ void split2(float v0, float v1, uint32_t& hi, uint32_t& lo) {
    uint32_t h;
    asm("cvt.rn.bf16x2.f32 %0, %1, %2;" : "=r"(h) : "f"(v1), "f"(v0));
    float h0 = __uint_as_float(h << 16);
    float h1 = __uint_as_float(h & 0xFFFF0000u);
    asm("cvt.rn.bf16x2.f32 %0, %1, %2;" : "=r"(lo) : "f"(v1 - h1), "f"(v0 - h0));
    hi = h;
}

// NOTE: non-volatile — lets ptxas reorder/pipeline MMAs and break C-chains.
__device__ __forceinline__ void mma_bf16(float* c, const uint32_t* a, uint32_t b0, uint32_t b1) {
    asm("mma.sync.aligned.m16n8k16.row.col.f32.bf16.bf16.f32 "
        "{%0,%1,%2,%3},{%4,%5,%6,%7},{%8,%9},{%0,%1,%2,%3};"
        : "+f"(c[0]), "+f"(c[1]), "+f"(c[2]), "+f"(c[3])
        : "r"(a[0]), "r"(a[1]), "r"(a[2]), "r"(a[3]), "r"(b0), "r"(b1));
}

__device__ __forceinline__ uint32_t smem_u32(const void* p) {
    return (uint32_t)__cvta_generic_to_shared(p);
}
__device__ __forceinline__ uint4 ldsm_x4(uint32_t addr) {
    uint4 r;
    asm("ldmatrix.sync.aligned.m8n8.x4.shared.b16 {%0,%1,%2,%3}, [%4];"
        : "=r"(r.x), "=r"(r.y), "=r"(r.z), "=r"(r.w) : "r"(addr));
    return r;
}
__device__ __forceinline__ uint4 ldsm_x4t(uint32_t addr) {
    uint4 r;
    asm("ldmatrix.sync.aligned.m8n8.x4.trans.shared.b16 {%0,%1,%2,%3}, [%4];"
        : "=r"(r.x), "=r"(r.y), "=r"(r.z), "=r"(r.w) : "r"(addr));
    return r;
}

// ---------------------------------------------------------------------------
// Kernel 1: QKV projection on tensor cores.
// Tile 128 tok x 128 out, k-step 32 (2 mma-k). 8 warps: 4 (tok) x 2 (out).
// x [cin][tok] staged hi/lo as-is; A-frags via ldmatrix.trans.
// w [out][cin] staged hi/lo; B-frags via ldmatrix.
// ---------------------------------------------------------------------------
__global__ __launch_bounds__(256, 2)
void qkv_proj_kernel(const float* __restrict__ x,
                     const float* __restrict__ qw, const float* __restrict__ qb,
                     const float* __restrict__ kw, const float* __restrict__ kb,
                     const float* __restrict__ vw, const float* __restrict__ vb)
{
    __shared__ uint16_t Axh[32][136], Axl[32][136];   // x tile, rows = cin
    __shared__ uint16_t Bwh[128][40], Bwl[128][40];   // w tile, rows = out

    const int tid  = threadIdx.x;
    const int lane = tid & 31, w = tid >> 5;
    const int g = lane >> 2, tig = lane & 3;
    const int wm = w & 3, wn = w >> 2;
    const int t0 = blockIdx.x * 128;
    const int nt = blockIdx.y;           // 0..11
    const int which = nt >> 2;           // 0=q 1=k 2=v
    const int o0 = (nt & 3) * 128;

    const float* wt  = (which == 0) ? qw : (which == 1) ? kw : vw;
    const float* bia = (which == 0) ? qb : (which == 1) ? kb : vb;
    uint16_t* ohi = (uint16_t*)((which == 0) ? g_qhi : (which == 1) ? g_khi : g_vhi);
    uint16_t* olo = (uint16_t*)((which == 0) ? g_qlo : (which == 1) ? g_klo : g_vlo);

    const uint32_t axh = smem_u32(Axh), axl = smem_u32(Axl);
    const uint32_t bwh = smem_u32(Bwh), bwl = smem_u32(Bwl);
    // ldmatrix per-lane address components
    const int arow = ((lane >> 4) & 1) * 8 + (lane & 7);           // within A (trans)
    const int acol = wm * 32 + ((lane >> 3) & 1) * 8;
    const int brow = ((lane >> 4) & 1) * 8 + (lane & 7);           // within B
    const int bcol = ((lane >> 3) & 1) * 8;

    float C[2][8][4] = {};

    for (int k0 = 0; k0 < CIN; k0 += 32) {
        __syncthreads();
        // stage x tile [32 cin][128 tok] hi/lo
        #pragma unroll
        for (int u = 0; u < 4; u++) {
            int f = tid + u * 256;
            int row = f >> 5, c4 = (f & 31) * 4;
            float4 v = *(const float4*)&x[(size_t)(k0 + row) * NTOK + t0 + c4];
            uint32_t h0, l0, h1, l1;
            split2(v.x, v.y, h0, l0);
            split2(v.z, v.w, h1, l1);
            uint2 uh; uh.x = h0; uh.y = h1;
            uint2 ul; ul.x = l0; ul.y = l1;
            *(uint2*)&Axh[row][c4] = uh;
            *(uint2*)&Axl[row][c4] = ul;
        }
        // stage w tile [128 out][32 cin] hi/lo
        #pragma unroll
        for (int u = 0; u < 4; u++) {
            int f = tid + u * 256;
            int row = f >> 3, c4 = (f & 7) * 4;
            float4 v = *(const float4*)&wt[(size_t)(o0 + row) * CIN + k0 + c4];
            uint32_t h0, l0, h1, l1;
            split2(v.x, v.y, h0, l0);
            split2(v.z, v.w, h1, l1);
            uint2 uh; uh.x = h0; uh.y = h1;
            uint2 ul; ul.x = l0; ul.y = l1;
            *(uint2*)&Bwh[row][c4] = uh;
            *(uint2*)&Bwl[row][c4] = ul;
        }
        __syncthreads();

        #pragma unroll
        for (int ks = 0; ks < 2; ks++) {
            uint32_t AH[2][4], AL[2][4];
            #pragma unroll
            for (int mf = 0; mf < 2; mf++) {
                uint32_t off = (uint32_t)(((ks * 16 + arow) * 136 + acol + mf * 16) * 2);
                uint4 a = ldsm_x4t(axh + off);
                AH[mf][0] = a.x; AH[mf][1] = a.y; AH[mf][2] = a.z; AH[mf][3] = a.w;
                uint4 b = ldsm_x4t(axl + off);
                AL[mf][0] = b.x; AL[mf][1] = b.y; AL[mf][2] = b.z; AL[mf][3] = b.w;
            }
            #pragma unroll
            for (int np = 0; np < 4; np++) {
                uint32_t off = (uint32_t)(((wn * 64 + np * 16 + brow) * 40 + ks * 16 + bcol) * 2);
                uint4 BH = ldsm_x4(bwh + off);
                uint4 BL = ldsm_x4(bwl + off);
                #pragma unroll
                for (int mf = 0; mf < 2; mf++) {
                    mma_bf16(C[mf][2*np],   AH[mf], BH.x, BH.y);
                    mma_bf16(C[mf][2*np+1], AH[mf], BH.z, BH.w);
                    mma_bf16(C[mf][2*np],   AH[mf], BL.x, BL.y);
                    mma_bf16(C[mf][2*np+1], AH[mf], BL.z, BL.w);
                    mma_bf16(C[mf][2*np],   AL[mf], BH.x, BH.y);
                    mma_bf16(C[mf][2*np+1], AL[mf], BH.z, BH.w);
                }
            }
        }
    }

    // epilogue: bias + hi/lo split store (row-major, coalesced-ish)
    #pragma unroll
    for (int mf = 0; mf < 2; mf++) {
        int r0 = t0 + wm * 32 + mf * 16 + g;
        #pragma unroll
        for (int n = 0; n < 8; n++) {
            int col = o0 + wn * 64 + n * 8 + 2 * tig;
            float b0 = bia[col], b1 = bia[col + 1];
            const float* c = C[mf][n];
            uint32_t h, l;
            split2(c[0] + b0, c[1] + b1, h, l);
            *(uint32_t*)(ohi + (size_t)r0 * CIN + col) = h;
            *(uint32_t*)(olo + (size_t)r0 * CIN + col) = l;
            split2(c[2] + b0, c[3] + b1, h, l);
            *(uint32_t*)(ohi + (size_t)(r0 + 8) * CIN + col) = h;
            *(uint32_t*)(olo + (size_t)(r0 + 8) * CIN + col) = l;
        }
    }
}

// ---------------------------------------------------------------------------
// Kernel 2: flash attention, tensor cores + ldmatrix. 8 warps, 128q x 128k.
// K frags: ldmatrix non-trans on K[key][d]. V frags: ldmatrix.trans on V[key][d].
// Q smem region aliased with K/V (Q frags extracted to regs before loop).
// ---------------------------------------------------------------------------
__global__ __launch_bounds__(256, 1)
void attn_kernel(const float* __restrict__ lqw)
{
    extern __shared__ uint16_t sm16[];
    // union: phase 0 = Q staging; phase 1 = K/V staging
    uint16_t* qhi = sm16;                  // 128*72
    uint16_t* qlo = sm16 + 9216;
    uint16_t* khi = sm16;                  // aliases Q region
    uint16_t* klo = sm16 + 9216;
    uint16_t* vhi = sm16 + 18432;
    uint16_t* vlo = sm16 + 27648;
    float*    lqs = (float*)(sm16 + 36864);   // 128 floats

    const int tid  = threadIdx.x;
    const int lane = tid & 31, w = tid >> 5;
    const int g = lane >> 2, tig = lane & 3;
    const int h  = blockIdx.y;
    const int q0 = blockIdx.x * 128;

    // ---- stage Q hi/lo, extract A-frags to registers ----
    for (int idx = tid; idx < 1024; idx += 256) {
        int r = idx >> 3, c4 = idx & 7;
        *(uint4*)(qhi + r * 72 + c4 * 8) =
            *((const uint4*)((const uint16_t*)g_qhi + (size_t)(q0 + r) * CIN + h * HD) + c4);
        *(uint4*)(qlo + r * 72 + c4 * 8) =
            *((const uint4*)((const uint16_t*)g_qlo + (size_t)(q0 + r) * CIN + h * HD) + c4);
    }
    __syncthreads();

    uint32_t qahi[4][4], qalo[4][4];
    {
        const uint32_t qhb = smem_u32(qhi), qlb = smem_u32(qlo);
        int qrow = (lane & 7) + ((lane >> 3) & 1) * 8;
        int qcol = ((lane >> 4) & 1) * 8;
        #pragma unroll
        for (int ks = 0; ks < 4; ks++) {
            uint32_t off = (uint32_t)(((w * 16 + qrow) * 72 + ks * 16 + qcol) * 2);
            uint4 a = ldsm_x4(qhb + off);
            qahi[ks][0] = a.x; qahi[ks][1] = a.y; qahi[ks][2] = a.z; qahi[ks][3] = a.w;
            uint4 b = ldsm_x4(qlb + off);
            qalo[ks][0] = b.x; qalo[ks][1] = b.y; qalo[ks][2] = b.z; qalo[ks][3] = b.w;
        }
    }

    const uint32_t khb = smem_u32(khi), klb = smem_u32(klo);
    const uint32_t vhb = smem_u32(vhi), vlb = smem_u32(vlo);
    const int krow = ((lane >> 4) & 1) * 8 + (lane & 7);
    const int kcol = ((lane >> 3) & 1) * 8;
    const int vrow = ((lane >> 3) & 1) * 8 + (lane & 7);
    const int vcol = ((lane >> 4) & 1) * 8;

    float O[8][4] = {};
    float m0 = -1e30f, m1 = -1e30f, l0 = 0.f, l1 = 0.f;

    #pragma unroll 1
    for (int kt = 0; kt < NTOK / 128; kt++) {
        __syncthreads();   // protect Q frags extraction (kt=0) / prior reads
        for (int idx = tid; idx < 1024; idx += 256) {
            int r = idx >> 3, c4 = idx & 7;
            size_t gofs = (size_t)(kt * 128 + r) * CIN + h * HD;
            *(uint4*)(khi + r * 72 + c4 * 8) = *((const uint4*)((const uint16_t*)g_khi + gofs) + c4);
            *(uint4*)(klo + r * 72 + c4 * 8) = *((const uint4*)((const uint16_t*)g_klo + gofs) + c4);
            *(uint4*)(vhi + r * 72 + c4 * 8) = *((const uint4*)((const uint16_t*)g_vhi + gofs) + c4);
            *(uint4*)(vlo + r * 72 + c4 * 8) = *((const uint4*)((const uint16_t*)g_vlo + gofs) + c4);
        }
        if (tid < 128) lqs[tid] = lqw[kt * 128 + tid];
        __syncthreads();

        // ---- S = Q K^T ----
        float s[16][4] = {};
        #pragma unroll
        for (int ks = 0; ks < 4; ks++) {
            #pragma unroll
            for (int np = 0; np < 8; np++) {
                uint32_t off = (uint32_t)(((np * 16 + krow) * 72 + ks * 16 + kcol) * 2);
                uint4 BH = ldsm_x4(khb + off);
                uint4 BL = ldsm_x4(klb + off);
                mma_bf16(s[2*np],   qahi[ks], BH.x, BH.y);
                mma_bf16(s[2*np+1], qahi[ks], BH.z, BH.w);
                mma_bf16(s[2*np],   qahi[ks], BL.x, BL.y);
                mma_bf16(s[2*np+1], qahi[ks], BL.z, BL.w);
                mma_bf16(s[2*np],   qalo[ks], BH.x, BH.y);
                mma_bf16(s[2*np+1], qalo[ks], BH.z, BH.w);
            }
        }

        // ---- online softmax in registers ----
        float mx0 = -1e30f, mx1 = -1e30f;
        #pragma unroll
        for (int n = 0; n < 16; n++) {
            float2 lw = *(const float2*)&lqs[n * 8 + 2 * tig];
            s[n][0] = fmaf(s[n][0], 0.125f, lw.x);
            s[n][1] = fmaf(s[n][1], 0.125f, lw.y);
            s[n][2] = fmaf(s[n][2], 0.125f, lw.x);
            s[n][3] = fmaf(s[n][3], 0.125f, lw.y);
            mx0 = fmaxf(mx0, fmaxf(s[n][0], s[n][1]));
            mx1 = fmaxf(mx1, fmaxf(s[n][2], s[n][3]));
        }
        mx0 = fmaxf(mx0, __shfl_xor_sync(0xffffffffu, mx0, 1));
        mx0 = fmaxf(mx0, __shfl_xor_sync(0xffffffffu, mx0, 2));
        mx1 = fmaxf(mx1, __shfl_xor_sync(0xffffffffu, mx1, 1));
        mx1 = fmaxf(mx1, __shfl_xor_sync(0xffffffffu, mx1, 2));

        float mn0 = fmaxf(m0, mx0), mn1 = fmaxf(m1, mx1);
        float al0 = fast_exp(m0 - mn0), al1 = fast_exp(m1 - mn1);
        m0 = mn0; m1 = mn1;

        float sum0 = 0.f, sum1 = 0.f;
        #pragma unroll
        for (int n = 0; n < 16; n++) {
            s[n][0] = fast_exp(s[n][0] - mn0);
            s[n][1] = fast_exp(s[n][1] - mn0);
            s[n][2] = fast_exp(s[n][2] - mn1);
            s[n][3] = fast_exp(s[n][3] - mn1);
            sum0 += s[n][0] + s[n][1];
            sum1 += s[n][2] + s[n][3];
        }
        sum0 += __shfl_xor_sync(0xffffffffu, sum0, 1);
        sum0 += __shfl_xor_sync(0xffffffffu, sum0, 2);
        sum1 += __shfl_xor_sync(0xffffffffu, sum1, 1);
        sum1 += __shfl_xor_sync(0xffffffffu, sum1, 2);
        l0 = fmaf(l0, al0, sum0);
        l1 = fmaf(l1, al1, sum1);

        #pragma unroll
        for (int nd = 0; nd < 8; nd++) {
            O[nd][0] *= al0; O[nd][1] *= al0;
            O[nd][2] *= al1; O[nd][3] *= al1;
        }

        // ---- O += P V ----
        #pragma unroll
        for (int c = 0; c < 8; c++) {
            uint32_t ah[4], al[4];
            split2(s[2*c][0],   s[2*c][1],   ah[0], al[0]);
            split2(s[2*c][2],   s[2*c][3],   ah[1], al[1]);
            split2(s[2*c+1][0], s[2*c+1][1], ah[2], al[2]);
            split2(s[2*c+1][2], s[2*c+1][3], ah[3], al[3]);
            #pragma unroll
            for (int ndp = 0; ndp < 4; ndp++) {
                uint32_t off = (uint32_t)(((c * 16 + vrow) * 72 + ndp * 16 + vcol) * 2);
                uint4 VH = ldsm_x4t(vhb + off);
                uint4 VL = ldsm_x4t(vlb + off);
                mma_bf16(O[2*ndp],   ah, VH.x, VH.y);
                mma_bf16(O[2*ndp+1], ah, VH.z, VH.w);
                mma_bf16(O[2*ndp],   ah, VL.x, VL.y);
                mma_bf16(O[2*ndp+1], ah, VL.z, VL.w);
                mma_bf16(O[2*ndp],   al, VH.x, VH.y);
                mma_bf16(O[2*ndp+1], al, VH.z, VH.w);
            }
        }
    }

    // epilogue: normalize, write fp32 token-major
    float i0 = 1.0f / l0, i1 = 1.0f / l1;
    #pragma unroll
    for (int nd = 0; nd < 8; nd++) {
        float2 w0; w0.x = O[nd][0] * i0; w0.y = O[nd][1] * i0;
        float2 w1; w1.x = O[nd][2] * i1; w1.y = O[nd][3] * i1;
        *(float2*)&g_o[(size_t)(q0 + w * 16 + g)     * CIN + h * HD + nd * 8 + 2 * tig] = w0;
        *(float2*)&g_o[(size_t)(q0 + w * 16 + g + 8) * CIN + h * HD + nd * 8 + 2 * tig] = w1;
    }
}

// ---------------------------------------------------------------------------
// Kernel 3: output projection (fp32 SIMT).
// ---------------------------------------------------------------------------
__global__ __launch_bounds__(256)
void out_proj_kernel(const float* __restrict__ pw, const float* __restrict__ pb,
                     float* __restrict__ out)
{
    __shared__ float As[16][132];
    __shared__ float Bs[16][132];

    const int tid = threadIdx.x;
    const int tx = tid & 15, ty = tid >> 4;
    const int t0 = blockIdx.x * 128;
    const int o0 = blockIdx.y * 128;

    float acc[8][8] = {};

    for (int k0 = 0; k0 < CIN; k0 += 16) {
        #pragma unroll
        for (int u = 0; u < 2; u++) {
            int f = tid + u * 256;
            int ro = f >> 2, kq = (f & 3) * 4;
            float4 av = *(const float4*)&pw[(size_t)(o0 + ro) * CIN + k0 + kq];
            As[kq+0][ro] = av.x; As[kq+1][ro] = av.y;
            As[kq+2][ro] = av.z; As[kq+3][ro] = av.w;
            float4 bv = *(const float4*)&g_o[(size_t)(t0 + ro) * CIN + k0 + kq];
            Bs[kq+0][ro] = bv.x; Bs[kq+1][ro] = bv.y;
            Bs[kq+2][ro] = bv.z; Bs[kq+3][ro] = bv.w;
        }
        __syncthreads();
        #pragma unroll
        for (int k = 0; k < 16; k++) {
            float4 a0 = *(const float4*)&As[k][ty * 4];
            float4 a1 = *(const float4*)&As[k][64 + ty * 4];
            float4 b0 = *(const float4*)&Bs[k][tx * 4];
            float4 b1 = *(const float4*)&Bs[k][64 + tx * 4];
            float av[8] = {a0.x,a0.y,a0.z,a0.w,a1.x,a1.y,a1.z,a1.w};
            float bv[8] = {b0.x,b0.y,b0.z,b0.w,b1.x,b1.y,b1.z,b1.w};
            #pragma unroll
            for (int i = 0; i < 8; i++)
                #pragma unroll
                for (int j = 0; j < 8; j++)
                    acc[i][j] = fmaf(av[i], bv[j], acc[i][j]);
        }
        __syncthreads();
    }

    #pragma unroll
    for (int i = 0; i < 8; i++) {
        int orow = o0 + ((i < 4) ? (ty * 4 + i) : (64 + ty * 4 + i - 4));
        float bias = pb[orow];
        float4 r0, r1;
        r0.x = acc[i][0] + bias; r0.y = acc[i][1] + bias;
        r0.z = acc[i][2] + bias; r0.w = acc[i][3] + bias;
        r1.x = acc[i][4] + bias; r1.y = acc[i][5] + bias;
        r1.z = acc[i][6] + bias; r1.w = acc[i][7] + bias;
        *(float4*)&out[(size_t)orow * NTOK + t0 + tx * 4]      = r0;
        *(float4*)&out[(size_t)orow * NTOK + t0 + 64 + tx * 4] = r1;
    }
}

// ---------------------------------------------------------------------------
extern "C" void kernel_launch(void* const* d_in, const int* in_sizes, int n_in,
                              void* d_out, int out_size)
{
    (void)in_sizes; (void)n_in; (void)out_size;
    const float* x   = (const float*)d_in[0];
    const float* qw  = (const float*)d_in[1];
    const float* qb  = (const float*)d_in[2];
    const float* kw  = (const float*)d_in[3];
    const float* kb  = (const float*)d_in[4];
    const float* vw  = (const float*)d_in[5];
    const float* vb  = (const float*)d_in[6];
    const float* pw  = (const float*)d_in[7];
    const float* pb  = (const float*)d_in[8];
    const float* lqw = (const float*)d_in[9];
    float* out = (float*)d_out;

    // attn smem: 4 x 128*72 bf16 (K/V hi/lo; Q aliased) + 128 f32 = 74,240 B
    const int attn_smem = 4 * 128 * 72 * 2 + 128 * 4;
    cudaFuncSetAttribute(attn_kernel, cudaFuncAttributeMaxDynamicSharedMemorySize, attn_smem);

    qkv_proj_kernel<<<dim3(NTOK / 128, 12), 256>>>(x, qw, qb, kw, kb, vw, vb);
    attn_kernel<<<dim3(NTOK / 128, HEADS), 256, attn_smem>>>(lqw);
    out_proj_kernel<<<dim3(NTOK / 128, CIN / 128), 256>>>(pw, pb, out);
}

// round 7
// speedup vs baseline: 5.0035x; 1.1882x over previous
#include <cuda_runtime.h>
#include <cuda_bf16.h>
#include <cstdint>

// ---------------------------------------------------------------------------
// AttentionS2: B=1, C=512, HEADS=8, hd=64, tokens HW=4096
// All three GEMM stages on tensor cores (bf16 hi/lo 3-term, fp32 accum).
// Attention mainloop: 2-stage cp.async pipeline (copy kt+1 || compute kt).
// ---------------------------------------------------------------------------

#define NTOK 4096
#define CIN  512
#define HEADS 8
#define HD 64

// bf16 hi/lo splits, all token-major [tok][chan]
__device__ __nv_bfloat16 g_qhi[NTOK * CIN], g_qlo[NTOK * CIN];
__device__ __nv_bfloat16 g_khi[NTOK * CIN], g_klo[NTOK * CIN];
__device__ __nv_bfloat16 g_vhi[NTOK * CIN], g_vlo[NTOK * CIN];
__device__ __nv_bfloat16 g_ohi[NTOK * CIN], g_olo[NTOK * CIN];

// fast exp on FMA/ALU pipes (avoids MUFU bottleneck)
__device__ __forceinline__ float fast_exp(float x) {
    x = fmaxf(x, -87.0f);
    float z = x * 1.4426950408889634f;
    float r = z + 12582912.0f;
    int   n = __float_as_int(r) - 0x4B400000;
    float f = z - (r - 12582912.0f);
    float p = 1.3333558e-4f;
    p = fmaf(p, f, 1.3336425e-3f);
    p = fmaf(p, f, 9.6181291e-3f);
    p = fmaf(p, f, 5.5504109e-2f);
    p = fmaf(p, f, 2.4022651e-1f);
    p = fmaf(p, f, 6.9314718e-1f);
    p = fmaf(p, f, 1.0f);
    return __int_as_float(__float_as_int(p) + (n << 23));
}

// split (v0,v1) into packed bf16x2 hi and lo residual; low half = v0
__device__ __forceinline__ void split2(float v0, float v1, uint32_t& hi, uint32_t& lo) {
    uint32_t h;
    asm("cvt.rn.bf16x2.f32 %0, %1, %2;" : "=r"(h) : "f"(v1), "f"(v0));
    float h0 = __uint_as_float(h << 16);
    float h1 = __uint_as_float(h & 0xFFFF0000u);
    asm("cvt.rn.bf16x2.f32 %0, %1, %2;" : "=r"(lo) : "f"(v1 - h1), "f"(v0 - h0));
    hi = h;
}

// non-volatile: lets ptxas reorder/pipeline MMAs and break C-chains
__device__ __forceinline__ void mma_bf16(float* c, const uint32_t* a, uint32_t b0, uint32_t b1) {
    asm("mma.sync.aligned.m16n8k16.row.col.f32.bf16.bf16.f32 "
        "{%0,%1,%2,%3},{%4,%5,%6,%7},{%8,%9},{%0,%1,%2,%3};"
        : "+f"(c[0]), "+f"(c[1]), "+f"(c[2]), "+f"(c[3])
        : "r"(a[0]), "r"(a[1]), "r"(a[2]), "r"(a[3]), "r"(b0), "r"(b1));
}

__device__ __forceinline__ uint32_t smem_u32(const void* p) {
    return (uint32_t)__cvta_generic_to_shared(p);
}
__device__ __forceinline__ uint4 ldsm_x4(uint32_t addr) {
    uint4 r;
    asm("ldmatrix.sync.aligned.m8n8.x4.shared.b16 {%0,%1,%2,%3}, [%4];"
        : "=r"(r.x), "=r"(r.y), "=r"(r.z), "=r"(r.w) : "r"(addr));
    return r;
}
__device__ __forceinline__ uint4 ldsm_x4t(uint32_t addr) {
    uint4 r;
    asm("ldmatrix.sync.aligned.m8n8.x4.trans.shared.b16 {%0,%1,%2,%3}, [%4];"
        : "=r"(r.x), "=r"(r.y), "=r"(r.z), "=r"(r.w) : "r"(addr));
    return r;
}
__device__ __forceinline__ void cp16(uint32_t dst, const void* src) {
    asm volatile("cp.async.cg.shared.global [%0], [%1], 16;" :: "r"(dst), "l"(src));
}
__device__ __forceinline__ void cp4(uint32_t dst, const void* src) {
    asm volatile("cp.async.ca.shared.global [%0], [%1], 4;" :: "r"(dst), "l"(src));
}
__device__ __forceinline__ void cp_commit() {
    asm volatile("cp.async.commit_group;");
}
template <int N>
__device__ __forceinline__ void cp_wait() {
    asm volatile("cp.async.wait_group %0;" :: "n"(N));
}

// ---------------------------------------------------------------------------
// Kernel 1: QKV projection on tensor cores (unchanged; 80us known-good)
// ---------------------------------------------------------------------------
__global__ __launch_bounds__(256, 2)
void qkv_proj_kernel(const float* __restrict__ x,
                     const float* __restrict__ qw, const float* __restrict__ qb,
                     const float* __restrict__ kw, const float* __restrict__ kb,
                     const float* __restrict__ vw, const float* __restrict__ vb)
{
    __shared__ uint16_t Axh[32][136], Axl[32][136];
    __shared__ uint16_t Bwh[128][40], Bwl[128][40];

    const int tid  = threadIdx.x;
    const int lane = tid & 31, w = tid >> 5;
    const int g = lane >> 2, tig = lane & 3;
    const int wm = w & 3, wn = w >> 2;
    const int t0 = blockIdx.x * 128;
    const int nt = blockIdx.y;
    const int which = nt >> 2;
    const int o0 = (nt & 3) * 128;

    const float* wt  = (which == 0) ? qw : (which == 1) ? kw : vw;
    const float* bia = (which == 0) ? qb : (which == 1) ? kb : vb;
    uint16_t* ohi = (uint16_t*)((which == 0) ? g_qhi : (which == 1) ? g_khi : g_vhi);
    uint16_t* olo = (uint16_t*)((which == 0) ? g_qlo : (which == 1) ? g_klo : g_vlo);

    const uint32_t axh = smem_u32(Axh), axl = smem_u32(Axl);
    const uint32_t bwh = smem_u32(Bwh), bwl = smem_u32(Bwl);
    const int arow = ((lane >> 4) & 1) * 8 + (lane & 7);
    const int acol = wm * 32 + ((lane >> 3) & 1) * 8;
    const int brow = ((lane >> 4) & 1) * 8 + (lane & 7);
    const int bcol = ((lane >> 3) & 1) * 8;

    float C[2][8][4] = {};

    for (int k0 = 0; k0 < CIN; k0 += 32) {
        __syncthreads();
        #pragma unroll
        for (int u = 0; u < 4; u++) {
            int f = tid + u * 256;
            int row = f >> 5, c4 = (f & 31) * 4;
            float4 v = *(const float4*)&x[(size_t)(k0 + row) * NTOK + t0 + c4];
            uint32_t h0, l0, h1, l1;
            split2(v.x, v.y, h0, l0);
            split2(v.z, v.w, h1, l1);
            uint2 uh; uh.x = h0; uh.y = h1;
            uint2 ul; ul.x = l0; ul.y = l1;
            *(uint2*)&Axh[row][c4] = uh;
            *(uint2*)&Axl[row][c4] = ul;
        }
        #pragma unroll
        for (int u = 0; u < 4; u++) {
            int f = tid + u * 256;
            int row = f >> 3, c4 = (f & 7) * 4;
            float4 v = *(const float4*)&wt[(size_t)(o0 + row) * CIN + k0 + c4];
            uint32_t h0, l0, h1, l1;
            split2(v.x, v.y, h0, l0);
            split2(v.z, v.w, h1, l1);
            uint2 uh; uh.x = h0; uh.y = h1;
            uint2 ul; ul.x = l0; ul.y = l1;
            *(uint2*)&Bwh[row][c4] = uh;
            *(uint2*)&Bwl[row][c4] = ul;
        }
        __syncthreads();

        #pragma unroll
        for (int ks = 0; ks < 2; ks++) {
            uint32_t AH[2][4], AL[2][4];
            #pragma unroll
            for (int mf = 0; mf < 2; mf++) {
                uint32_t off = (uint32_t)(((ks * 16 + arow) * 136 + acol + mf * 16) * 2);
                uint4 a = ldsm_x4t(axh + off);
                AH[mf][0] = a.x; AH[mf][1] = a.y; AH[mf][2] = a.z; AH[mf][3] = a.w;
                uint4 b = ldsm_x4t(axl + off);
                AL[mf][0] = b.x; AL[mf][1] = b.y; AL[mf][2] = b.z; AL[mf][3] = b.w;
            }
            #pragma unroll
            for (int np = 0; np < 4; np++) {
                uint32_t off = (uint32_t)(((wn * 64 + np * 16 + brow) * 40 + ks * 16 + bcol) * 2);
                uint4 BH = ldsm_x4(bwh + off);
                uint4 BL = ldsm_x4(bwl + off);
                #pragma unroll
                for (int mf = 0; mf < 2; mf++) {
                    mma_bf16(C[mf][2*np],   AH[mf], BH.x, BH.y);
                    mma_bf16(C[mf][2*np+1], AH[mf], BH.z, BH.w);
                    mma_bf16(C[mf][2*np],   AH[mf], BL.x, BL.y);
                    mma_bf16(C[mf][2*np+1], AH[mf], BL.z, BL.w);
                    mma_bf16(C[mf][2*np],   AL[mf], BH.x, BH.y);
                    mma_bf16(C[mf][2*np+1], AL[mf], BH.z, BH.w);
                }
            }
        }
    }

    #pragma unroll
    for (int mf = 0; mf < 2; mf++) {
        int r0 = t0 + wm * 32 + mf * 16 + g;
        #pragma unroll
        for (int n = 0; n < 8; n++) {
            int col = o0 + wn * 64 + n * 8 + 2 * tig;
            float b0 = bia[col], b1 = bia[col + 1];
            const float* c = C[mf][n];
            uint32_t h, l;
            split2(c[0] + b0, c[1] + b1, h, l);
            *(uint32_t*)(ohi + (size_t)r0 * CIN + col) = h;
            *(uint32_t*)(olo + (size_t)r0 * CIN + col) = l;
            split2(c[2] + b0, c[3] + b1, h, l);
            *(uint32_t*)(ohi + (size_t)(r0 + 8) * CIN + col) = h;
            *(uint32_t*)(olo + (size_t)(r0 + 8) * CIN + col) = l;
        }
    }
}

// ---------------------------------------------------------------------------
// Kernel 2: flash attention, tensor cores + ldmatrix + 2-stage cp.async.
// smem layout (uint16 units):
//   Q hi [0,9216), Q lo [9216,18432)
//   stage s: base 18432 + s*36864: khi +0, klo +9216, vhi +18432, vlo +27648
//   lqs (float[2][128]) at uint16 offset 92160
// Sub-buffer byte offsets within a stage: 0, 9216*2, 18432*2, 27648*2.
// ---------------------------------------------------------------------------
#define ATTN_SMEM_BYTES (92160 * 2 + 2 * 128 * 4)

__global__ __launch_bounds__(256, 1)
void attn_kernel(const float* __restrict__ lqw)
{
    extern __shared__ uint16_t sm16[];

    const int tid  = threadIdx.x;
    const int lane = tid & 31, w = tid >> 5;
    const int g = lane >> 2, tig = lane & 3;
    const int h  = blockIdx.y;
    const int q0 = blockIdx.x * 128;

    const uint32_t smb = smem_u32(sm16);
    const uint32_t qhb = smb, qlb = smb + 9216 * 2;
    const uint32_t stage_base[2] = { smb + 18432 * 2, smb + (18432 + 36864) * 2 };
    const uint32_t lqs_b = smb + 92160 * 2;
    float* lqs = (float*)(sm16 + 92160);

    // byte offsets of sub-buffers within a stage
    const uint32_t KLO_OFF = 9216 * 2;
    const uint32_t VHI_OFF = 18432 * 2;
    const uint32_t VLO_OFF = 27648 * 2;

    // ---- prologue: cp.async Q (group 0), KV tile 0 + lqw0 (group 1) ----
    #pragma unroll
    for (int u = 0; u < 4; u++) {
        int idx = tid + u * 256;
        int r = idx >> 3, c4 = idx & 7;
        size_t gofs = (size_t)(q0 + r) * CIN + h * HD + c4 * 8;
        uint32_t so = (uint32_t)((r * 72 + c4 * 8) * 2);
        cp16(qhb + so, (const uint16_t*)g_qhi + gofs);
        cp16(qlb + so, (const uint16_t*)g_qlo + gofs);
    }
    cp_commit();
    {
        uint32_t sb = stage_base[0];
        #pragma unroll
        for (int u = 0; u < 4; u++) {
            int idx = tid + u * 256;
            int r = idx >> 3, c4 = idx & 7;
            size_t gofs = (size_t)r * CIN + h * HD + c4 * 8;
            uint32_t so = (uint32_t)((r * 72 + c4 * 8) * 2);
            cp16(sb + so,           (const uint16_t*)g_khi + gofs);
            cp16(sb + KLO_OFF + so, (const uint16_t*)g_klo + gofs);
            cp16(sb + VHI_OFF + so, (const uint16_t*)g_vhi + gofs);
            cp16(sb + VLO_OFF + so, (const uint16_t*)g_vlo + gofs);
        }
        if (tid < 128) cp4(lqs_b + tid * 4, lqw + tid);
    }
    cp_commit();

    // ---- wait for Q, extract A-fragments to registers ----
    cp_wait<1>();
    __syncthreads();

    uint32_t qahi[4][4], qalo[4][4];
    {
        int qrow = (lane & 7) + ((lane >> 3) & 1) * 8;
        int qcol = ((lane >> 4) & 1) * 8;
        #pragma unroll
        for (int ks = 0; ks < 4; ks++) {
            uint32_t off = (uint32_t)(((w * 16 + qrow) * 72 + ks * 16 + qcol) * 2);
            uint4 a = ldsm_x4(qhb + off);
            qahi[ks][0] = a.x; qahi[ks][1] = a.y; qahi[ks][2] = a.z; qahi[ks][3] = a.w;
            uint4 b = ldsm_x4(qlb + off);
            qalo[ks][0] = b.x; qalo[ks][1] = b.y; qalo[ks][2] = b.z; qalo[ks][3] = b.w;
        }
    }

    const int krow = ((lane >> 4) & 1) * 8 + (lane & 7);
    const int kcol = ((lane >> 3) & 1) * 8;
    const int vrow = ((lane >> 3) & 1) * 8 + (lane & 7);
    const int vcol = ((lane >> 4) & 1) * 8;

    float O[8][4] = {};
    float m0 = -1e30f, m1 = -1e30f, l0 = 0.f, l1 = 0.f;

    #pragma unroll 1
    for (int kt = 0; kt < NTOK / 128; kt++) {
        __syncthreads();   // all warps done computing kt-1 (buf (kt+1)&1 free)

        if (kt + 1 < NTOK / 128) {
            int ktn = kt + 1;
            uint32_t sb = stage_base[ktn & 1];
            #pragma unroll
            for (int u = 0; u < 4; u++) {
                int idx = tid + u * 256;
                int r = idx >> 3, c4 = idx & 7;
                size_t gofs = (size_t)(ktn * 128 + r) * CIN + h * HD + c4 * 8;
                uint32_t so = (uint32_t)((r * 72 + c4 * 8) * 2);
                cp16(sb + so,           (const uint16_t*)g_khi + gofs);
                cp16(sb + KLO_OFF + so, (const uint16_t*)g_klo + gofs);
                cp16(sb + VHI_OFF + so, (const uint16_t*)g_vhi + gofs);
                cp16(sb + VLO_OFF + so, (const uint16_t*)g_vlo + gofs);
            }
            if (tid < 128) cp4(lqs_b + ((ktn & 1) * 128 + tid) * 4, lqw + ktn * 128 + tid);
            cp_commit();
            cp_wait<1>();   // tile kt arrived; kt+1 in flight
        } else {
            cp_wait<0>();   // last tile: drain everything
        }
        __syncthreads();

        const uint32_t sb  = stage_base[kt & 1];
        const uint32_t khb = sb,            klb = sb + KLO_OFF;
        const uint32_t vhb = sb + VHI_OFF,  vlb = sb + VLO_OFF;
        const float* lq = lqs + (kt & 1) * 128;

        // ---- S = Q K^T ----
        float s[16][4] = {};
        #pragma unroll
        for (int ks = 0; ks < 4; ks++) {
            #pragma unroll
            for (int np = 0; np < 8; np++) {
                uint32_t off = (uint32_t)(((np * 16 + krow) * 72 + ks * 16 + kcol) * 2);
                uint4 BH = ldsm_x4(khb + off);
                uint4 BL = ldsm_x4(klb + off);
                mma_bf16(s[2*np],   qahi[ks], BH.x, BH.y);
                mma_bf16(s[2*np+1], qahi[ks], BH.z, BH.w);
                mma_bf16(s[2*np],   qahi[ks], BL.x, BL.y);
                mma_bf16(s[2*np+1], qahi[ks], BL.z, BL.w);
                mma_bf16(s[2*np],   qalo[ks], BH.x, BH.y);
                mma_bf16(s[2*np+1], qalo[ks], BH.z, BH.w);
            }
        }

        // ---- online softmax in registers ----
        float mx0 = -1e30f, mx1 = -1e30f;
        #pragma unroll
        for (int n = 0; n < 16; n++) {
            float2 lw = *(const float2*)&lq[n * 8 + 2 * tig];
            s[n][0] = fmaf(s[n][0], 0.125f, lw.x);
            s[n][1] = fmaf(s[n][1], 0.125f, lw.y);
            s[n][2] = fmaf(s[n][2], 0.125f, lw.x);
            s[n][3] = fmaf(s[n][3], 0.125f, lw.y);
            mx0 = fmaxf(mx0, fmaxf(s[n][0], s[n][1]));
            mx1 = fmaxf(mx1, fmaxf(s[n][2], s[n][3]));
        }
        mx0 = fmaxf(mx0, __shfl_xor_sync(0xffffffffu, mx0, 1));
        mx0 = fmaxf(mx0, __shfl_xor_sync(0xffffffffu, mx0, 2));
        mx1 = fmaxf(mx1, __shfl_xor_sync(0xffffffffu, mx1, 1));
        mx1 = fmaxf(mx1, __shfl_xor_sync(0xffffffffu, mx1, 2));

        float mn0 = fmaxf(m0, mx0), mn1 = fmaxf(m1, mx1);
        float al0 = fast_exp(m0 - mn0), al1 = fast_exp(m1 - mn1);
        m0 = mn0; m1 = mn1;

        float sum0 = 0.f, sum1 = 0.f;
        #pragma unroll
        for (int n = 0; n < 16; n++) {
            s[n][0] = fast_exp(s[n][0] - mn0);
            s[n][1] = fast_exp(s[n][1] - mn0);
            s[n][2] = fast_exp(s[n][2] - mn1);
            s[n][3] = fast_exp(s[n][3] - mn1);
            sum0 += s[n][0] + s[n][1];
            sum1 += s[n][2] + s[n][3];
        }
        sum0 += __shfl_xor_sync(0xffffffffu, sum0, 1);
        sum0 += __shfl_xor_sync(0xffffffffu, sum0, 2);
        sum1 += __shfl_xor_sync(0xffffffffu, sum1, 1);
        sum1 += __shfl_xor_sync(0xffffffffu, sum1, 2);
        l0 = fmaf(l0, al0, sum0);
        l1 = fmaf(l1, al1, sum1);

        #pragma unroll
        for (int nd = 0; nd < 8; nd++) {
            O[nd][0] *= al0; O[nd][1] *= al0;
            O[nd][2] *= al1; O[nd][3] *= al1;
        }

        // ---- O += P V ----
        #pragma unroll
        for (int c = 0; c < 8; c++) {
            uint32_t ah[4], al[4];
            split2(s[2*c][0],   s[2*c][1],   ah[0], al[0]);
            split2(s[2*c][2],   s[2*c][3],   ah[1], al[1]);
            split2(s[2*c+1][0], s[2*c+1][1], ah[2], al[2]);
            split2(s[2*c+1][2], s[2*c+1][3], ah[3], al[3]);
            #pragma unroll
            for (int ndp = 0; ndp < 4; ndp++) {
                uint32_t off = (uint32_t)(((c * 16 + vrow) * 72 + ndp * 16 + vcol) * 2);
                uint4 VH = ldsm_x4t(vhb + off);
                uint4 VL = ldsm_x4t(vlb + off);
                mma_bf16(O[2*ndp],   ah, VH.x, VH.y);
                mma_bf16(O[2*ndp+1], ah, VH.z, VH.w);
                mma_bf16(O[2*ndp],   ah, VL.x, VL.y);
                mma_bf16(O[2*ndp+1], ah, VL.z, VL.w);
                mma_bf16(O[2*ndp],   al, VH.x, VH.y);
                mma_bf16(O[2*ndp+1], al, VH.z, VH.w);
            }
        }
    }

    // epilogue: normalize, write bf16 hi/lo token-major
    float i0 = 1.0f / l0, i1 = 1.0f / l1;
    uint16_t* ohi = (uint16_t*)g_ohi;
    uint16_t* olo = (uint16_t*)g_olo;
    #pragma unroll
    for (int nd = 0; nd < 8; nd++) {
        size_t c0 = (size_t)(q0 + w * 16 + g)     * CIN + h * HD + nd * 8 + 2 * tig;
        size_t c1 = (size_t)(q0 + w * 16 + g + 8) * CIN + h * HD + nd * 8 + 2 * tig;
        uint32_t hh, ll;
        split2(O[nd][0] * i0, O[nd][1] * i0, hh, ll);
        *(uint32_t*)(ohi + c0) = hh;
        *(uint32_t*)(olo + c0) = ll;
        split2(O[nd][2] * i1, O[nd][3] * i1, hh, ll);
        *(uint32_t*)(ohi + c1) = hh;
        *(uint32_t*)(olo + c1) = ll;
    }
}

// ---------------------------------------------------------------------------
// Kernel 3: output projection on tensor cores.
// out[o][t] = sum_c pw[o][c]*o_act[t][c] + pb[o]
// ---------------------------------------------------------------------------
__global__ __launch_bounds__(256, 2)
void out_proj_kernel(const float* __restrict__ pw, const float* __restrict__ pb,
                     float* __restrict__ out)
{
    __shared__ uint16_t Awh[128][40], Awl[128][40];   // pw tile [o][c]
    __shared__ uint16_t Bah[128][40], Bal[128][40];   // act tile [t][c]

    const int tid  = threadIdx.x;
    const int lane = tid & 31, w = tid >> 5;
    const int g = lane >> 2, tig = lane & 3;
    const int wm = w & 3, wn = w >> 2;     // wm: o quarter, wn: t half
    const int t0 = blockIdx.x * 128;
    const int o0 = blockIdx.y * 128;

    const uint32_t awh = smem_u32(Awh), awl = smem_u32(Awl);
    const uint32_t bah = smem_u32(Bah), bal = smem_u32(Bal);
    const int arow = (lane & 7) + ((lane >> 3) & 1) * 8;   // A pattern
    const int acol = ((lane >> 4) & 1) * 8;
    const int brow = ((lane >> 4) & 1) * 8 + (lane & 7);   // B pattern
    const int bcol = ((lane >> 3) & 1) * 8;

    float C[2][8][4] = {};

    for (int k0 = 0; k0 < CIN; k0 += 32) {
        __syncthreads();
        // stage pw tile [128 o][32 c], split hi/lo
        #pragma unroll
        for (int u = 0; u < 4; u++) {
            int f = tid + u * 256;
            int row = f >> 3, c4 = (f & 7) * 4;
            float4 v = *(const float4*)&pw[(size_t)(o0 + row) * CIN + k0 + c4];
            uint32_t h0, l0, h1, l1;
            split2(v.x, v.y, h0, l0);
            split2(v.z, v.w, h1, l1);
            uint2 uh; uh.x = h0; uh.y = h1;
            uint2 ul; ul.x = l0; ul.y = l1;
            *(uint2*)&Awh[row][c4] = uh;
            *(uint2*)&Awl[row][c4] = ul;
        }
        // stage act tile [128 t][32 c] (already bf16 hi/lo in gmem)
        #pragma unroll
        for (int u = 0; u < 2; u++) {
            int f = tid + u * 256;
            int row = f >> 2, c8 = (f & 3) * 8;
            *(uint4*)&Bah[row][c8] =
                *(const uint4*)((const uint16_t*)g_ohi + (size_t)(t0 + row) * CIN + k0 + c8);
            *(uint4*)&Bal[row][c8] =
                *(const uint4*)((const uint16_t*)g_olo + (size_t)(t0 + row) * CIN + k0 + c8);
        }
        __syncthreads();

        #pragma unroll
        for (int ks = 0; ks < 2; ks++) {
            uint32_t AH[2][4], AL[2][4];
            #pragma unroll
            for (int mf = 0; mf < 2; mf++) {
                uint32_t off = (uint32_t)(((wm * 32 + mf * 16 + arow) * 40 + ks * 16 + acol) * 2);
                uint4 a = ldsm_x4(awh + off);
                AH[mf][0] = a.x; AH[mf][1] = a.y; AH[mf][2] = a.z; AH[mf][3] = a.w;
                uint4 b = ldsm_x4(awl + off);
                AL[mf][0] = b.x; AL[mf][1] = b.y; AL[mf][2] = b.z; AL[mf][3] = b.w;
            }
            #pragma unroll
            for (int np = 0; np < 4; np++) {
                uint32_t off = (uint32_t)(((wn * 64 + np * 16 + brow) * 40 + ks * 16 + bcol) * 2);
                uint4 BH = ldsm_x4(bah + off);
                uint4 BL = ldsm_x4(bal + off);
                #pragma unroll
                for (int mf = 0; mf < 2; mf++) {
                    mma_bf16(C[mf][2*np],   AH[mf], BH.x, BH.y);
                    mma_bf16(C[mf][2*np+1], AH[mf], BH.z, BH.w);
                    mma_bf16(C[mf][2*np],   AH[mf], BL.x, BL.y);
                    mma_bf16(C[mf][2*np+1], AH[mf], BL.z, BL.w);
                    mma_bf16(C[mf][2*np],   AL[mf], BH.x, BH.y);
                    mma_bf16(C[mf][2*np+1], AL[mf], BH.z, BH.w);
                }
            }
        }
    }

    // epilogue: C[m=o][n=t] + bias -> out[o][t]
    #pragma unroll
    for (int mf = 0; mf < 2; mf++) {
        int orow0 = o0 + wm * 32 + mf * 16 + g;
        float b0 = pb[orow0], b1 = pb[orow0 + 8];
        #pragma unroll
        for (int n = 0; n < 8; n++) {
            int tcol = t0 + wn * 64 + n * 8 + 2 * tig;
            const float* c = C[mf][n];
            float2 r0; r0.x = c[0] + b0; r0.y = c[1] + b0;
            float2 r1; r1.x = c[2] + b1; r1.y = c[3] + b1;
            *(float2*)&out[(size_t)orow0 * NTOK + tcol]       = r0;
            *(float2*)&out[(size_t)(orow0 + 8) * NTOK + tcol] = r1;
        }
    }
}

// ---------------------------------------------------------------------------
extern "C" void kernel_launch(void* const* d_in, const int* in_sizes, int n_in,
                              void* d_out, int out_size)
{
    (void)in_sizes; (void)n_in; (void)out_size;
    const float* x   = (const float*)d_in[0];
    const float* qw  = (const float*)d_in[1];
    const float* qb  = (const float*)d_in[2];
    const float* kw  = (const float*)d_in[3];
    const float* kb  = (const float*)d_in[4];
    const float* vw  = (const float*)d_in[5];
    const float* vb  = (const float*)d_in[6];
    const float* pw  = (const float*)d_in[7];
    const float* pb  = (const float*)d_in[8];
    const float* lqw = (const float*)d_in[9];
    float* out = (float*)d_out;

    cudaFuncSetAttribute(attn_kernel, cudaFuncAttributeMaxDynamicSharedMemorySize,
                         ATTN_SMEM_BYTES);

    qkv_proj_kernel<<<dim3(NTOK / 128, 12), 256>>>(x, qw, qb, kw, kb, vw, vb);
    attn_kernel<<<dim3(NTOK / 128, HEADS), 256, ATTN_SMEM_BYTES>>>(lqw);
    out_proj_kernel<<<dim3(NTOK / 128, CIN / 128), 256>>>(pw, pb, out);
}